// round 11
// baseline (speedup 1.0000x reference)
#include <cuda_runtime.h>
#include <cuda_fp16.h>
#include <cstdint>

// ---------------------------------------------------------------------------
// FastAttention — linear attention with ReLU feature maps.
// Big GEMMs: fp16 mma m16n8k16, CTA 128x128x64, 128 thr (warp 64x64),
// 3-stage cp.async (144B rows), 2 CTAs/SM. kv/attn on tensor cores.
// This round: GEMM1 split into (phiK|V) + (phiQ) and a second stream so
//   round(query) overlaps the weight prologue, and kv+reduce overlap GEMM1b.
// ---------------------------------------------------------------------------

// ------------------------- device scratch (no allocs) ----------------------
__device__ __align__(16) __half g_XH[(size_t)16384 * 1024];
__device__ __align__(16) __half g_WBIGH[(size_t)3072 * 1024];
__device__ __align__(16) __half g_WORH[(size_t)1024 * 1024];
__device__ __align__(16) __half g_ATTNH[(size_t)16384 * 1024];
__device__ __align__(16) __half g_PHIVH[(size_t)16384 * 3072];
__device__ __align__(16) __half g_KVHT[64 * 64 * 64];   // [bh][e][d] fp16
__device__ float g_KSUM[64 * 64];
__device__ float g_KVP[4 * 64 * 64 * 64];
__device__ float g_KSP[4 * 64 * 64];

// ------------------------- helpers ------------------------------------------
__device__ __forceinline__ uint32_t smem_u32(const void* p) {
    uint32_t a;
    asm("{ .reg .u64 t; cvta.to.shared.u64 t, %1; cvt.u32.u64 %0, t; }"
        : "=r"(a) : "l"(p));
    return a;
}
__device__ __forceinline__ void cp16(uint32_t dst, const void* src) {
    asm volatile("cp.async.cg.shared.global [%0], [%1], 16;" :: "r"(dst), "l"(src));
}
__device__ __forceinline__ void ldsm_x4(uint32_t& r0, uint32_t& r1,
                                        uint32_t& r2, uint32_t& r3, uint32_t a) {
    asm volatile("ldmatrix.sync.aligned.m8n8.x4.shared.b16 {%0,%1,%2,%3}, [%4];"
                 : "=r"(r0), "=r"(r1), "=r"(r2), "=r"(r3) : "r"(a));
}
__device__ __forceinline__ void ldsm_x4_t(uint32_t& r0, uint32_t& r1,
                                          uint32_t& r2, uint32_t& r3, uint32_t a) {
    asm volatile("ldmatrix.sync.aligned.m8n8.x4.trans.shared.b16 {%0,%1,%2,%3}, [%4];"
                 : "=r"(r0), "=r"(r1), "=r"(r2), "=r"(r3) : "r"(a));
}
__device__ __forceinline__ void mma_f16(float* c, uint32_t a0, uint32_t a1,
                                        uint32_t a2, uint32_t a3,
                                        uint32_t b0, uint32_t b1) {
    asm volatile(
        "mma.sync.aligned.m16n8k16.row.col.f32.f16.f16.f32 "
        "{%0,%1,%2,%3}, {%4,%5,%6,%7}, {%8,%9}, {%0,%1,%2,%3};"
        : "+f"(c[0]), "+f"(c[1]), "+f"(c[2]), "+f"(c[3])
        : "r"(a0), "r"(a1), "r"(a2), "r"(a3), "r"(b0), "r"(b1));
}

// ------------------------- K1: fused per-head weights (fp16 out) ------------
__global__ __launch_bounds__(256)
void build_weff_kernel(const float* __restrict__ Wq,
                       const float* __restrict__ Wk,
                       const float* __restrict__ P)
{
    int bid   = blockIdx.x;
    int which = bid >> 8;
    int rem   = bid & 255;
    int h     = rem >> 4;
    int chunk = rem & 15;
    const float* W = which ? Wk : Wq;

    __shared__ float Psh[64][64];
    __shared__ float Wsh[64][64];
    int tid = threadIdx.x;

#pragma unroll
    for (int i = 0; i < 4; i++) {
        int f = tid + i * 256;
        int e = f >> 4, c4 = (f & 15) << 2;
        *(float4*)&Psh[e][c4] = *(const float4*)(P + (size_t)h * 4096 + f * 4);
        *(float4*)&Wsh[e][c4] =
            *(const float4*)(W + (size_t)(h * 64 + e) * 1024 + chunk * 64 + c4);
    }
    __syncthreads();

    int dp = tid & 63;
    int dg = tid >> 6;
    float acc[16];
#pragma unroll
    for (int j = 0; j < 16; j++) acc[j] = 0.f;
#pragma unroll 4
    for (int e = 0; e < 64; e++) {
        float p = Psh[e][dp];
#pragma unroll
        for (int j = 0; j < 16; j++)
            acc[j] += p * Wsh[e][dg * 16 + j];
    }
    __half* dst = g_WBIGH + (size_t)(which * 1024 + h * 64 + dp) * 1024
                          + chunk * 64 + dg * 16;
#pragma unroll
    for (int j = 0; j < 16; j += 2)
        *(half2*)(dst + j) = __floats2half2_rn(acc[j], acc[j + 1]);
}

// ------------------------- K2: copy Wv (fp16) --------------------------------
__global__ __launch_bounds__(256)
void copy_wv_kernel(const float* __restrict__ Wv)
{
    int row = blockIdx.x;
    int tid = threadIdx.x;
    float4 v = *(const float4*)(Wv + (size_t)row * 1024 + tid * 4);
    __half* dst = g_WBIGH + (size_t)(2048 + row) * 1024 + tid * 4;
    *(half2*)(dst)     = __floats2half2_rn(v.x, v.y);
    *(half2*)(dst + 2) = __floats2half2_rn(v.z, v.w);
}

// ------------------------- round fp32 -> fp16 --------------------------------
__global__ __launch_bounds__(256)
void round_half_kernel(const float* __restrict__ src, __half* __restrict__ dst)
{
    size_t i = ((size_t)blockIdx.x * 256 + threadIdx.x) * 4;
    float4 v = *(const float4*)(src + i);
    *(half2*)(dst + i)     = __floats2half2_rn(v.x, v.y);
    *(half2*)(dst + i + 2) = __floats2half2_rn(v.z, v.w);
}

// ------------------------- fp16 mma GEMM (k64, frag double-buffer) ----------
constexpr int HROW_B   = 144;                      // 128B data + 16B pad
constexpr int H_TILE_B = 128 * HROW_B;             // 18432 per A/B tile
constexpr int H_STAGE  = 2 * H_TILE_B;             // 36864
constexpr int H_STAGES = 3;
constexpr int GEMM_SMEM = H_STAGES * H_STAGE;      // 110592 B

template<typename OutT, bool RELU, bool BIAS>
__global__ __launch_bounds__(128, 2)
void gemm_mma(const __half* __restrict__ A, const __half* __restrict__ Bm,
              const float* __restrict__ bias, OutT* __restrict__ C,
              int M, int N, int K, int relu_cols)
{
    extern __shared__ char smem[];
    const int tid = threadIdx.x;
    const int m0 = blockIdx.y * 128;
    const int n0 = blockIdx.x * 128;
    const int KT = K >> 6;                         // chunks of 64 halfs

    const uint32_t smem_base = smem_u32(smem);

    auto load_stage = [&](int kt, int buf) {
        uint32_t ab = smem_base + buf * H_STAGE;
        uint32_t bb = ab + H_TILE_B;
        const __half* Asrc = A + (size_t)m0 * K + kt * 64;
        const __half* Bsrc = Bm + (size_t)n0 * K + kt * 64;
#pragma unroll
        for (int j = 0; j < 8; j++) {              // 1024 cp16 per tile
            int o = tid + j * 128;
            int r = o >> 3, cc = o & 7;
            cp16(ab + (uint32_t)(r * HROW_B + cc * 16),
                 Asrc + (size_t)r * K + cc * 8);
            cp16(bb + (uint32_t)(r * HROW_B + cc * 16),
                 Bsrc + (size_t)r * K + cc * 8);
        }
    };

    const int wid  = tid >> 5;
    const int lane = tid & 31;
    const int wm = wid & 1;
    const int wn = wid >> 1;
    const int g  = lane >> 2;
    const int tg = lane & 3;

    const uint32_t aoff = (uint32_t)((wm * 64 + (lane & 15)) * HROW_B
                                     + ((lane & 16) ? 16 : 0));
    const uint32_t boff = (uint32_t)((wn * 64 + ((lane & 16) ? 8 : 0)
                                      + (lane & 7)) * HROW_B
                                     + ((lane & 8) ? 16 : 0));

    float acc[4][8][4];
#pragma unroll
    for (int mi = 0; mi < 4; mi++)
#pragma unroll
        for (int ni = 0; ni < 8; ni++)
#pragma unroll
            for (int q = 0; q < 4; q++) acc[mi][ni][q] = 0.f;

    uint32_t fa[2][4][4], fb[2][8][2];

    auto load_frags = [&](uint32_t As, uint32_t Bs, int ks, int buf) {
        uint32_t kofs = (uint32_t)ks * 32;
#pragma unroll
        for (int mi = 0; mi < 4; mi++)
            ldsm_x4(fa[buf][mi][0], fa[buf][mi][1], fa[buf][mi][2],
                    fa[buf][mi][3], As + aoff + mi * (16 * HROW_B) + kofs);
#pragma unroll
        for (int nj = 0; nj < 4; nj++)
            ldsm_x4(fb[buf][nj * 2][0], fb[buf][nj * 2][1],
                    fb[buf][nj * 2 + 1][0], fb[buf][nj * 2 + 1][1],
                    Bs + boff + nj * (16 * HROW_B) + kofs);
    };

    load_stage(0, 0);
    asm volatile("cp.async.commit_group;" ::: "memory");
    load_stage(1, 1);
    asm volatile("cp.async.commit_group;" ::: "memory");

    for (int kt = 0; kt < KT; kt++) {
        asm volatile("cp.async.wait_group 1;" ::: "memory");
        __syncthreads();

        if (kt + 2 < KT) load_stage(kt + 2, (kt + 2) % 3);
        asm volatile("cp.async.commit_group;" ::: "memory");

        uint32_t As = smem_base + (kt % 3) * H_STAGE;
        uint32_t Bs = As + H_TILE_B;

        load_frags(As, Bs, 0, 0);
#pragma unroll
        for (int ks = 0; ks < 4; ks++) {
            int cur = ks & 1;
            if (ks < 3) load_frags(As, Bs, ks + 1, cur ^ 1);
#pragma unroll
            for (int mi = 0; mi < 4; mi++)
#pragma unroll
                for (int ni = 0; ni < 8; ni++)
                    mma_f16(acc[mi][ni],
                            fa[cur][mi][0], fa[cur][mi][1],
                            fa[cur][mi][2], fa[cur][mi][3],
                            fb[cur][ni][0], fb[cur][ni][1]);
        }
    }

#pragma unroll
    for (int mi = 0; mi < 4; mi++) {
        int row0 = m0 + wm * 64 + mi * 16 + g;
#pragma unroll
        for (int ni = 0; ni < 8; ni++) {
            int col = n0 + wn * 64 + ni * 8 + tg * 2;
            float2 v0 = make_float2(acc[mi][ni][0], acc[mi][ni][1]);
            float2 v1 = make_float2(acc[mi][ni][2], acc[mi][ni][3]);
            if (BIAS) {
                float2 b2 = *(const float2*)(bias + col);
                v0.x += b2.x; v0.y += b2.y;
                v1.x += b2.x; v1.y += b2.y;
            }
            if (RELU && col < relu_cols) {
                v0.x = fmaxf(v0.x, 0.f); v0.y = fmaxf(v0.y, 0.f);
                v1.x = fmaxf(v1.x, 0.f); v1.y = fmaxf(v1.y, 0.f);
            }
            if constexpr (sizeof(OutT) == 2) {
                *(half2*)((__half*)C + (size_t)row0 * N + col) =
                    __floats2half2_rn(v0.x, v0.y);
                *(half2*)((__half*)C + (size_t)(row0 + 8) * N + col) =
                    __floats2half2_rn(v1.x, v1.y);
            } else {
                *(float2*)((float*)C + (size_t)row0 * N + col) = v0;
                *(float2*)((float*)C + (size_t)(row0 + 8) * N + col) = v1;
            }
        }
    }
}

// ------------------------- K4: kv + ksum via tensor cores (4 splits) ---------
constexpr int KVROW_B   = 144;
constexpr int KV_TILE_B = 64 * KVROW_B;            // 9216
constexpr int KV_STAGE  = 2 * KV_TILE_B;           // 18432
constexpr int KV_SMEM   = 3 * KV_STAGE;            // 55296

__global__ __launch_bounds__(128)
void kv_mma_kernel()
{
    extern __shared__ char skv[];
    const uint32_t sb = smem_u32(skv);
    const int tid = threadIdx.x;
    const int wid = tid >> 5;
    const int lane = tid & 31;
    const int split = blockIdx.x;                  // 0..3
    const int bh = blockIdx.y;
    const int b = bh >> 4, h = bh & 15;
    const size_t base_row = (size_t)b * 4096 + split * 1024;
    const __half* PKg = g_PHIVH + 1024 + h * 64;
    const __half* VVg = g_PHIVH + 2048 + h * 64;

    auto load_chunk = [&](int c, int buf) {
        uint32_t pb = sb + buf * KV_STAGE;
        uint32_t vb = pb + KV_TILE_B;
        size_t row0 = base_row + c * 64;
#pragma unroll
        for (int j = 0; j < 4; j++) {
            int o = tid + j * 128;
            int r = o >> 3, cc = o & 7;
            size_t off = (row0 + r) * 3072 + cc * 8;
            cp16(pb + (uint32_t)(r * KVROW_B + cc * 16), PKg + off);
            cp16(vb + (uint32_t)(r * KVROW_B + cc * 16), VVg + off);
        }
    };

    const uint32_t a_off = (uint32_t)((((lane & 16) ? 8 : 0) + (lane & 7)) * KVROW_B
                                      + wid * 32 + ((lane & 8) ? 16 : 0));
    const uint32_t b_off = (uint32_t)((((lane & 8) ? 8 : 0) + (lane & 7)) * KVROW_B
                                      + ((lane & 16) ? 16 : 0));

    float acc[8][4];
#pragma unroll
    for (int ni = 0; ni < 8; ni++)
#pragma unroll
        for (int q = 0; q < 4; q++) acc[ni][q] = 0.f;
    float ks = 0.f;

    load_chunk(0, 0);
    asm volatile("cp.async.commit_group;" ::: "memory");
    load_chunk(1, 1);
    asm volatile("cp.async.commit_group;" ::: "memory");

    for (int c = 0; c < 16; c++) {
        asm volatile("cp.async.wait_group 1;" ::: "memory");
        __syncthreads();
        if (c + 2 < 16) load_chunk(c + 2, (c + 2) % 3);
        asm volatile("cp.async.commit_group;" ::: "memory");

        uint32_t pb = sb + (c % 3) * KV_STAGE;
        uint32_t vb = pb + KV_TILE_B;

        if (tid < 64) {
            const __half* pk = (const __half*)(skv + (c % 3) * KV_STAGE);
#pragma unroll 8
            for (int n = 0; n < 64; n++)
                ks += __half2float(*(const __half*)((const char*)pk
                                                    + n * KVROW_B + tid * 2));
        }

#pragma unroll
        for (int kk = 0; kk < 4; kk++) {
            uint32_t a0, a1, a2, a3;
            ldsm_x4_t(a0, a1, a2, a3, pb + kk * (16 * KVROW_B) + a_off);
#pragma unroll
            for (int eb = 0; eb < 4; eb++) {
                uint32_t r0, r1, r2, r3;
                ldsm_x4_t(r0, r1, r2, r3,
                          vb + kk * (16 * KVROW_B) + b_off + eb * 32);
                mma_f16(acc[eb * 2],     a0, a1, a2, a3, r0, r1);
                mma_f16(acc[eb * 2 + 1], a0, a1, a2, a3, r2, r3);
            }
        }
    }

    float* dst = g_KVP + (size_t)(split * 64 + bh) * 4096;
    int g = lane >> 2, tg = lane & 3;
#pragma unroll
    for (int ni = 0; ni < 8; ni++) {
        int e = ni * 8 + tg * 2;
        int d0 = wid * 16 + g;
        dst[d0 * 64 + e]           = acc[ni][0];
        dst[d0 * 64 + e + 1]       = acc[ni][1];
        dst[(d0 + 8) * 64 + e]     = acc[ni][2];
        dst[(d0 + 8) * 64 + e + 1] = acc[ni][3];
    }
    if (tid < 64) g_KSP[(split * 64 + bh) * 64 + tid] = ks;
}

// ------------------------- K5: reduction -> fp16 transposed kv ---------------
__global__ __launch_bounds__(256)
void kv_reduce_kernel()
{
    int idx = blockIdx.x * 256 + threadIdx.x;
    if (idx < 64 * 4096) {
        int bh = idx >> 12, r = idx & 4095;
        float s = 0.f;
#pragma unroll
        for (int sp = 0; sp < 4; sp++)
            s += g_KVP[(size_t)(sp * 64 + bh) * 4096 + r];
        int d = r >> 6, e = r & 63;
        g_KVHT[(bh << 12) + (e << 6) + d] = __float2half(s);
    } else {
        int j = idx - 64 * 4096;
        if (j < 64 * 64) {
            int bh = j >> 6, d = j & 63;
            float s = 0.f;
#pragma unroll
            for (int sp = 0; sp < 4; sp++)
                s += g_KSP[(sp * 64 + bh) * 64 + d];
            g_KSUM[j] = s;
        }
    }
}

// ------------------------- K6: attn via tensor cores -------------------------
__global__ __launch_bounds__(128)
void attn_mma_kernel()
{
    __shared__ __align__(16) char sPQ[128 * 144];
    __shared__ __align__(16) char sKV[64 * 144];
    __shared__ float sDen[128];
    __shared__ float sKS[64];

    const int tid = threadIdx.x;
    const int wid = tid >> 5;
    const int lane = tid & 31;
    const int chunk = blockIdx.x;
    const int bh = blockIdx.y;
    const int b = bh >> 4, h = bh & 15;
    const size_t m0 = (size_t)b * 4096 + chunk * 128;

    const uint32_t pqb = smem_u32(sPQ);
    const uint32_t kvb = smem_u32(sKV);

    const __half* PQg = g_PHIVH + h * 64;
#pragma unroll
    for (int j = 0; j < 8; j++) {
        int o = tid + j * 128;
        int r = o >> 3, cc = o & 7;
        cp16(pqb + (uint32_t)(r * 144 + cc * 16), PQg + (m0 + r) * 3072 + cc * 8);
    }
    const __half* KVg = g_KVHT + ((size_t)bh << 12);
#pragma unroll
    for (int j = 0; j < 4; j++) {
        int o = tid + j * 128;
        int r = o >> 3, cc = o & 7;
        cp16(kvb + (uint32_t)(r * 144 + cc * 16), KVg + r * 64 + cc * 8);
    }
    asm volatile("cp.async.commit_group;" ::: "memory");
    if (tid < 64) sKS[tid] = g_KSUM[bh * 64 + tid];
    asm volatile("cp.async.wait_group 0;" ::: "memory");
    __syncthreads();

    {
        const __half* pq = (const __half*)(sPQ + tid * 144);
        float den = 0.f;
#pragma unroll 16
        for (int d = 0; d < 64; d++)
            den += __half2float(pq[d]) * sKS[d];
        sDen[tid] = 1.0f / (0.125f * den + 1e-8f);
    }

    const uint32_t aoff = pqb + (uint32_t)((wid * 32 + (lane & 15)) * 144
                                           + ((lane & 16) ? 16 : 0));
    const uint32_t boff = kvb + (uint32_t)((((lane & 16) ? 8 : 0) + (lane & 7)) * 144
                                           + ((lane & 8) ? 16 : 0));

    float acc[2][8][4];
#pragma unroll
    for (int mi = 0; mi < 2; mi++)
#pragma unroll
        for (int ni = 0; ni < 8; ni++)
#pragma unroll
            for (int q = 0; q < 4; q++) acc[mi][ni][q] = 0.f;

#pragma unroll
    for (int ksb = 0; ksb < 4; ksb++) {
        uint32_t kofs = ksb * 32;
        uint32_t af[2][4];
#pragma unroll
        for (int mi = 0; mi < 2; mi++)
            ldsm_x4(af[mi][0], af[mi][1], af[mi][2], af[mi][3],
                    aoff + mi * (16 * 144) + kofs);
        uint32_t bf[8][2];
#pragma unroll
        for (int nj = 0; nj < 4; nj++)
            ldsm_x4(bf[nj * 2][0], bf[nj * 2][1],
                    bf[nj * 2 + 1][0], bf[nj * 2 + 1][1],
                    boff + nj * (16 * 144) + kofs);
#pragma unroll
        for (int mi = 0; mi < 2; mi++)
#pragma unroll
            for (int ni = 0; ni < 8; ni++)
                mma_f16(acc[mi][ni], af[mi][0], af[mi][1], af[mi][2],
                        af[mi][3], bf[ni][0], bf[ni][1]);
    }
    __syncthreads();

    const int g = lane >> 2, tg = lane & 3;
#pragma unroll
    for (int mi = 0; mi < 2; mi++) {
        int row = wid * 32 + mi * 16 + g;
        float inv0 = sDen[row], inv1 = sDen[row + 8];
        __half* dst0 = g_ATTNH + (m0 + row) * 1024 + h * 64;
#pragma unroll
        for (int ni = 0; ni < 8; ni++) {
            int e = ni * 8 + tg * 2;
            *(half2*)(dst0 + e) =
                __floats2half2_rn(acc[mi][ni][0] * inv0, acc[mi][ni][1] * inv0);
            *(half2*)(dst0 + 8 * 1024 + e) =
                __floats2half2_rn(acc[mi][ni][2] * inv1, acc[mi][ni][3] * inv1);
        }
    }
}

// ------------------------- launch -------------------------------------------
extern "C" void kernel_launch(void* const* d_in, const int* in_sizes, int n_in,
                              void* d_out, int out_size)
{
    const float* query = (const float*)d_in[0];
    const float* Wq    = (const float*)d_in[1];
    const float* Wk    = (const float*)d_in[2];
    const float* Wv    = (const float*)d_in[3];
    const float* P     = (const float*)d_in[4];
    const float* Wo    = (const float*)d_in[5];
    const float* bo    = (const float*)d_in[6];
    float* out = (float*)d_out;

    void *p_xh, *p_wbigh, *p_worh, *p_attnh, *p_phivh;
    cudaGetSymbolAddress(&p_xh,     g_XH);
    cudaGetSymbolAddress(&p_wbigh,  g_WBIGH);
    cudaGetSymbolAddress(&p_worh,   g_WORH);
    cudaGetSymbolAddress(&p_attnh,  g_ATTNH);
    cudaGetSymbolAddress(&p_phivh,  g_PHIVH);

    // one-time infra (created on the first, non-captured, correctness call)
    static cudaStream_t s1 = nullptr;
    static cudaEvent_t evFork = nullptr, evQ = nullptr, evG1a = nullptr,
                       evK = nullptr;
    if (!s1) {
        cudaStreamCreateWithFlags(&s1, cudaStreamNonBlocking);
        cudaEventCreateWithFlags(&evFork, cudaEventDisableTiming);
        cudaEventCreateWithFlags(&evQ,    cudaEventDisableTiming);
        cudaEventCreateWithFlags(&evG1a,  cudaEventDisableTiming);
        cudaEventCreateWithFlags(&evK,    cudaEventDisableTiming);

        cudaFuncSetAttribute((const void*)gemm_mma<__half, true, false>,
                             cudaFuncAttributeMaxDynamicSharedMemorySize,
                             GEMM_SMEM);
        cudaFuncSetAttribute((const void*)gemm_mma<float, false, true>,
                             cudaFuncAttributeMaxDynamicSharedMemorySize,
                             GEMM_SMEM);
        cudaFuncSetAttribute((const void*)kv_mma_kernel,
                             cudaFuncAttributeMaxDynamicSharedMemorySize,
                             KV_SMEM);
    }

    // fork: s1 rounds the query concurrently with the weight prologue
    cudaEventRecord(evFork, 0);
    cudaStreamWaitEvent(s1, evFork, 0);
    round_half_kernel<<<16384, 256, 0, s1>>>(query, (__half*)p_xh);
    cudaEventRecord(evQ, s1);

    build_weff_kernel<<<512, 256>>>(Wq, Wk, P);
    copy_wv_kernel<<<1024, 256>>>(Wv);
    round_half_kernel<<<1024, 256>>>(Wo, (__half*)p_worh);

    cudaStreamWaitEvent(0, evQ, 0);

    // GEMM1a: phiK|V columns [1024,3072) — relu on local cols [0,1024)
    gemm_mma<__half, true, false><<<dim3(16, 128), 128, GEMM_SMEM>>>(
        (const __half*)p_xh, (const __half*)p_wbigh + (size_t)1024 * 1024,
        nullptr, (__half*)p_phivh + 1024, 16384, 3072, 1024, 1024);
    cudaEventRecord(evG1a, 0);

    // kv+reduce on s1, overlapping GEMM1b on stream 0
    cudaStreamWaitEvent(s1, evG1a, 0);
    kv_mma_kernel<<<dim3(4, 64), 128, KV_SMEM, s1>>>();
    kv_reduce_kernel<<<1040, 256, 0, s1>>>();
    cudaEventRecord(evK, s1);

    // GEMM1b: phiQ columns [0,1024) — relu on all
    gemm_mma<__half, true, false><<<dim3(8, 128), 128, GEMM_SMEM>>>(
        (const __half*)p_xh, (const __half*)p_wbigh, nullptr,
        (__half*)p_phivh, 16384, 3072, 1024, 1024);

    cudaStreamWaitEvent(0, evK, 0);
    attn_mma_kernel<<<dim3(32, 64), 128>>>();   // writes fp16 ATTN

    // out = ATTNH @ WORH^T + bo (fp32 out)
    gemm_mma<float, false, true><<<dim3(8, 128), 128, GEMM_SMEM>>>(
        (const __half*)p_attnh, (const __half*)p_worh, bo, out,
        16384, 1024, 1024, 0);
}

// round 12
// speedup vs baseline: 1.0293x; 1.0293x over previous
#include <cuda_runtime.h>
#include <cuda_fp16.h>
#include <cstdint>

// ---------------------------------------------------------------------------
// FastAttention — linear attention with ReLU feature maps.
// Big GEMMs: fp16 mma m16n8k16, CTA 128x128x64, 128 thr (warp 64x64),
// 3-stage cp.async (144B rows), 2 CTAs/SM. kv/attn on tensor cores.
// This round: fused prologue (weff + Wv copy + Wo round + query round in ONE
// launch), single stream, R9 GEMM/kv structure restored.
// ---------------------------------------------------------------------------

// ------------------------- device scratch (no allocs) ----------------------
__device__ __align__(16) __half g_XH[(size_t)16384 * 1024];
__device__ __align__(16) __half g_WBIGH[(size_t)3072 * 1024];
__device__ __align__(16) __half g_WORH[(size_t)1024 * 1024];
__device__ __align__(16) __half g_ATTNH[(size_t)16384 * 1024];
__device__ __align__(16) __half g_PHIVH[(size_t)16384 * 3072];
__device__ __align__(16) __half g_KVHT[64 * 64 * 64];   // [bh][e][d] fp16
__device__ float g_KSUM[64 * 64];
__device__ float g_KVP[8 * 64 * 64 * 64];
__device__ float g_KSP[8 * 64 * 64];

// ------------------------- helpers ------------------------------------------
__device__ __forceinline__ uint32_t smem_u32(const void* p) {
    uint32_t a;
    asm("{ .reg .u64 t; cvta.to.shared.u64 t, %1; cvt.u32.u64 %0, t; }"
        : "=r"(a) : "l"(p));
    return a;
}
__device__ __forceinline__ void cp16(uint32_t dst, const void* src) {
    asm volatile("cp.async.cg.shared.global [%0], [%1], 16;" :: "r"(dst), "l"(src));
}
__device__ __forceinline__ void ldsm_x4(uint32_t& r0, uint32_t& r1,
                                        uint32_t& r2, uint32_t& r3, uint32_t a) {
    asm volatile("ldmatrix.sync.aligned.m8n8.x4.shared.b16 {%0,%1,%2,%3}, [%4];"
                 : "=r"(r0), "=r"(r1), "=r"(r2), "=r"(r3) : "r"(a));
}
__device__ __forceinline__ void ldsm_x4_t(uint32_t& r0, uint32_t& r1,
                                          uint32_t& r2, uint32_t& r3, uint32_t a) {
    asm volatile("ldmatrix.sync.aligned.m8n8.x4.trans.shared.b16 {%0,%1,%2,%3}, [%4];"
                 : "=r"(r0), "=r"(r1), "=r"(r2), "=r"(r3) : "r"(a));
}
__device__ __forceinline__ void mma_f16(float* c, uint32_t a0, uint32_t a1,
                                        uint32_t a2, uint32_t a3,
                                        uint32_t b0, uint32_t b1) {
    asm volatile(
        "mma.sync.aligned.m16n8k16.row.col.f32.f16.f16.f32 "
        "{%0,%1,%2,%3}, {%4,%5,%6,%7}, {%8,%9}, {%0,%1,%2,%3};"
        : "+f"(c[0]), "+f"(c[1]), "+f"(c[2]), "+f"(c[3])
        : "r"(a0), "r"(a1), "r"(a2), "r"(a3), "r"(b0), "r"(b1));
}

// ------------------------- fused prologue ------------------------------------
// blocks [0,512):      Weff fold (Wq/Wk x per-head P) -> WBIGH fp16
// blocks [512,1536):   Wv rows -> WBIGH fp16
// blocks [1536,2560):  Wo -> WORH fp16
// blocks [2560,18944): query -> XH fp16
__global__ __launch_bounds__(256)
void prologue_kernel(const float* __restrict__ Wq,
                     const float* __restrict__ Wk,
                     const float* __restrict__ P,
                     const float* __restrict__ Wv,
                     const float* __restrict__ query,
                     const float* __restrict__ Wo)
{
    int bid = blockIdx.x;
    int tid = threadIdx.x;

    if (bid < 512) {
        // ---- weff fold ----
        int which = bid >> 8;
        int rem   = bid & 255;
        int h     = rem >> 4;
        int chunk = rem & 15;
        const float* W = which ? Wk : Wq;

        __shared__ float Psh[64][64];
        __shared__ float Wsh[64][64];
#pragma unroll
        for (int i = 0; i < 4; i++) {
            int f = tid + i * 256;
            int e = f >> 4, c4 = (f & 15) << 2;
            *(float4*)&Psh[e][c4] = *(const float4*)(P + (size_t)h * 4096 + f * 4);
            *(float4*)&Wsh[e][c4] =
                *(const float4*)(W + (size_t)(h * 64 + e) * 1024 + chunk * 64 + c4);
        }
        __syncthreads();

        int dp = tid & 63;
        int dg = tid >> 6;
        float acc[16];
#pragma unroll
        for (int j = 0; j < 16; j++) acc[j] = 0.f;
#pragma unroll 4
        for (int e = 0; e < 64; e++) {
            float p = Psh[e][dp];
#pragma unroll
            for (int j = 0; j < 16; j++)
                acc[j] += p * Wsh[e][dg * 16 + j];
        }
        __half* dst = g_WBIGH + (size_t)(which * 1024 + h * 64 + dp) * 1024
                              + chunk * 64 + dg * 16;
#pragma unroll
        for (int j = 0; j < 16; j += 2)
            *(half2*)(dst + j) = __floats2half2_rn(acc[j], acc[j + 1]);
    } else if (bid < 1536) {
        // ---- copy Wv ----
        int row = bid - 512;
        float4 v = *(const float4*)(Wv + (size_t)row * 1024 + tid * 4);
        __half* dst = g_WBIGH + (size_t)(2048 + row) * 1024 + tid * 4;
        *(half2*)(dst)     = __floats2half2_rn(v.x, v.y);
        *(half2*)(dst + 2) = __floats2half2_rn(v.z, v.w);
    } else if (bid < 2560) {
        // ---- round Wo ----
        size_t i = ((size_t)(bid - 1536) * 256 + tid) * 4;
        float4 v = *(const float4*)(Wo + i);
        *(half2*)(g_WORH + i)     = __floats2half2_rn(v.x, v.y);
        *(half2*)(g_WORH + i + 2) = __floats2half2_rn(v.z, v.w);
    } else {
        // ---- round query ----
        size_t i = ((size_t)(bid - 2560) * 256 + tid) * 4;
        float4 v = *(const float4*)(query + i);
        *(half2*)(g_XH + i)     = __floats2half2_rn(v.x, v.y);
        *(half2*)(g_XH + i + 2) = __floats2half2_rn(v.z, v.w);
    }
}

// ------------------------- fp16 mma GEMM (k64, frag double-buffer) ----------
constexpr int HROW_B   = 144;                      // 128B data + 16B pad
constexpr int H_TILE_B = 128 * HROW_B;             // 18432 per A/B tile
constexpr int H_STAGE  = 2 * H_TILE_B;             // 36864
constexpr int H_STAGES = 3;
constexpr int GEMM_SMEM = H_STAGES * H_STAGE;      // 110592 B

template<typename OutT, bool RELU, bool BIAS>
__global__ __launch_bounds__(128, 2)
void gemm_mma(const __half* __restrict__ A, const __half* __restrict__ Bm,
              const float* __restrict__ bias, OutT* __restrict__ C,
              int M, int N, int K, int relu_cols)
{
    extern __shared__ char smem[];
    const int tid = threadIdx.x;
    const int m0 = blockIdx.y * 128;
    const int n0 = blockIdx.x * 128;
    const int KT = K >> 6;                         // chunks of 64 halfs

    const uint32_t smem_base = smem_u32(smem);

    auto load_stage = [&](int kt, int buf) {
        uint32_t ab = smem_base + buf * H_STAGE;
        uint32_t bb = ab + H_TILE_B;
        const __half* Asrc = A + (size_t)m0 * K + kt * 64;
        const __half* Bsrc = Bm + (size_t)n0 * K + kt * 64;
#pragma unroll
        for (int j = 0; j < 8; j++) {              // 1024 cp16 per tile
            int o = tid + j * 128;
            int r = o >> 3, cc = o & 7;
            cp16(ab + (uint32_t)(r * HROW_B + cc * 16),
                 Asrc + (size_t)r * K + cc * 8);
            cp16(bb + (uint32_t)(r * HROW_B + cc * 16),
                 Bsrc + (size_t)r * K + cc * 8);
        }
    };

    const int wid  = tid >> 5;
    const int lane = tid & 31;
    const int wm = wid & 1;
    const int wn = wid >> 1;
    const int g  = lane >> 2;
    const int tg = lane & 3;

    const uint32_t aoff = (uint32_t)((wm * 64 + (lane & 15)) * HROW_B
                                     + ((lane & 16) ? 16 : 0));
    const uint32_t boff = (uint32_t)((wn * 64 + ((lane & 16) ? 8 : 0)
                                      + (lane & 7)) * HROW_B
                                     + ((lane & 8) ? 16 : 0));

    float acc[4][8][4];
#pragma unroll
    for (int mi = 0; mi < 4; mi++)
#pragma unroll
        for (int ni = 0; ni < 8; ni++)
#pragma unroll
            for (int q = 0; q < 4; q++) acc[mi][ni][q] = 0.f;

    uint32_t fa[2][4][4], fb[2][8][2];

    auto load_frags = [&](uint32_t As, uint32_t Bs, int ks, int buf) {
        uint32_t kofs = (uint32_t)ks * 32;
#pragma unroll
        for (int mi = 0; mi < 4; mi++)
            ldsm_x4(fa[buf][mi][0], fa[buf][mi][1], fa[buf][mi][2],
                    fa[buf][mi][3], As + aoff + mi * (16 * HROW_B) + kofs);
#pragma unroll
        for (int nj = 0; nj < 4; nj++)
            ldsm_x4(fb[buf][nj * 2][0], fb[buf][nj * 2][1],
                    fb[buf][nj * 2 + 1][0], fb[buf][nj * 2 + 1][1],
                    Bs + boff + nj * (16 * HROW_B) + kofs);
    };

    load_stage(0, 0);
    asm volatile("cp.async.commit_group;" ::: "memory");
    load_stage(1, 1);
    asm volatile("cp.async.commit_group;" ::: "memory");

    for (int kt = 0; kt < KT; kt++) {
        asm volatile("cp.async.wait_group 1;" ::: "memory");
        __syncthreads();

        if (kt + 2 < KT) load_stage(kt + 2, (kt + 2) % 3);
        asm volatile("cp.async.commit_group;" ::: "memory");

        uint32_t As = smem_base + (kt % 3) * H_STAGE;
        uint32_t Bs = As + H_TILE_B;

        load_frags(As, Bs, 0, 0);
#pragma unroll
        for (int ks = 0; ks < 4; ks++) {
            int cur = ks & 1;
            if (ks < 3) load_frags(As, Bs, ks + 1, cur ^ 1);
#pragma unroll
            for (int mi = 0; mi < 4; mi++)
#pragma unroll
                for (int ni = 0; ni < 8; ni++)
                    mma_f16(acc[mi][ni],
                            fa[cur][mi][0], fa[cur][mi][1],
                            fa[cur][mi][2], fa[cur][mi][3],
                            fb[cur][ni][0], fb[cur][ni][1]);
        }
    }

#pragma unroll
    for (int mi = 0; mi < 4; mi++) {
        int row0 = m0 + wm * 64 + mi * 16 + g;
#pragma unroll
        for (int ni = 0; ni < 8; ni++) {
            int col = n0 + wn * 64 + ni * 8 + tg * 2;
            float2 v0 = make_float2(acc[mi][ni][0], acc[mi][ni][1]);
            float2 v1 = make_float2(acc[mi][ni][2], acc[mi][ni][3]);
            if (BIAS) {
                float2 b2 = *(const float2*)(bias + col);
                v0.x += b2.x; v0.y += b2.y;
                v1.x += b2.x; v1.y += b2.y;
            }
            if (RELU && col < relu_cols) {
                v0.x = fmaxf(v0.x, 0.f); v0.y = fmaxf(v0.y, 0.f);
                v1.x = fmaxf(v1.x, 0.f); v1.y = fmaxf(v1.y, 0.f);
            }
            if constexpr (sizeof(OutT) == 2) {
                *(half2*)((__half*)C + (size_t)row0 * N + col) =
                    __floats2half2_rn(v0.x, v0.y);
                *(half2*)((__half*)C + (size_t)(row0 + 8) * N + col) =
                    __floats2half2_rn(v1.x, v1.y);
            } else {
                *(float2*)((float*)C + (size_t)row0 * N + col) = v0;
                *(float2*)((float*)C + (size_t)(row0 + 8) * N + col) = v1;
            }
        }
    }
}

// ------------------------- K4: kv + ksum via tensor cores (8 splits) ---------
constexpr int KVROW_B   = 144;
constexpr int KV_TILE_B = 64 * KVROW_B;            // 9216
constexpr int KV_STAGE  = 2 * KV_TILE_B;           // 18432
constexpr int KV_SMEM   = 3 * KV_STAGE;            // 55296

__global__ __launch_bounds__(128)
void kv_mma_kernel()
{
    extern __shared__ char skv[];
    const uint32_t sb = smem_u32(skv);
    const int tid = threadIdx.x;
    const int wid = tid >> 5;
    const int lane = tid & 31;
    const int split = blockIdx.x;
    const int bh = blockIdx.y;
    const int b = bh >> 4, h = bh & 15;
    const size_t base_row = (size_t)b * 4096 + split * 512;
    const __half* PKg = g_PHIVH + 1024 + h * 64;
    const __half* VVg = g_PHIVH + 2048 + h * 64;

    auto load_chunk = [&](int c, int buf) {
        uint32_t pb = sb + buf * KV_STAGE;
        uint32_t vb = pb + KV_TILE_B;
        size_t row0 = base_row + c * 64;
#pragma unroll
        for (int j = 0; j < 4; j++) {
            int o = tid + j * 128;
            int r = o >> 3, cc = o & 7;
            size_t off = (row0 + r) * 3072 + cc * 8;
            cp16(pb + (uint32_t)(r * KVROW_B + cc * 16), PKg + off);
            cp16(vb + (uint32_t)(r * KVROW_B + cc * 16), VVg + off);
        }
    };

    const uint32_t a_off = (uint32_t)((((lane & 16) ? 8 : 0) + (lane & 7)) * KVROW_B
                                      + wid * 32 + ((lane & 8) ? 16 : 0));
    const uint32_t b_off = (uint32_t)((((lane & 8) ? 8 : 0) + (lane & 7)) * KVROW_B
                                      + ((lane & 16) ? 16 : 0));

    float acc[8][4];
#pragma unroll
    for (int ni = 0; ni < 8; ni++)
#pragma unroll
        for (int q = 0; q < 4; q++) acc[ni][q] = 0.f;
    float ks = 0.f;

    load_chunk(0, 0);
    asm volatile("cp.async.commit_group;" ::: "memory");
    load_chunk(1, 1);
    asm volatile("cp.async.commit_group;" ::: "memory");

    for (int c = 0; c < 8; c++) {
        asm volatile("cp.async.wait_group 1;" ::: "memory");
        __syncthreads();
        if (c + 2 < 8) load_chunk(c + 2, (c + 2) % 3);
        asm volatile("cp.async.commit_group;" ::: "memory");

        uint32_t pb = sb + (c % 3) * KV_STAGE;
        uint32_t vb = pb + KV_TILE_B;

        if (tid < 64) {
            const __half* pk = (const __half*)(skv + (c % 3) * KV_STAGE);
#pragma unroll 8
            for (int n = 0; n < 64; n++)
                ks += __half2float(*(const __half*)((const char*)pk
                                                    + n * KVROW_B + tid * 2));
        }

#pragma unroll
        for (int kk = 0; kk < 4; kk++) {
            uint32_t a0, a1, a2, a3;
            ldsm_x4_t(a0, a1, a2, a3, pb + kk * (16 * KVROW_B) + a_off);
#pragma unroll
            for (int eb = 0; eb < 4; eb++) {
                uint32_t r0, r1, r2, r3;
                ldsm_x4_t(r0, r1, r2, r3,
                          vb + kk * (16 * KVROW_B) + b_off + eb * 32);
                mma_f16(acc[eb * 2],     a0, a1, a2, a3, r0, r1);
                mma_f16(acc[eb * 2 + 1], a0, a1, a2, a3, r2, r3);
            }
        }
    }

    float* dst = g_KVP + (size_t)(split * 64 + bh) * 4096;
    int g = lane >> 2, tg = lane & 3;
#pragma unroll
    for (int ni = 0; ni < 8; ni++) {
        int e = ni * 8 + tg * 2;
        int d0 = wid * 16 + g;
        dst[d0 * 64 + e]           = acc[ni][0];
        dst[d0 * 64 + e + 1]       = acc[ni][1];
        dst[(d0 + 8) * 64 + e]     = acc[ni][2];
        dst[(d0 + 8) * 64 + e + 1] = acc[ni][3];
    }
    if (tid < 64) g_KSP[(split * 64 + bh) * 64 + tid] = ks;
}

// ------------------------- K5: reduction -> fp16 transposed kv ---------------
__global__ __launch_bounds__(256)
void kv_reduce_kernel()
{
    int idx = blockIdx.x * 256 + threadIdx.x;
    if (idx < 64 * 4096) {
        int bh = idx >> 12, r = idx & 4095;
        float s = 0.f;
#pragma unroll
        for (int sp = 0; sp < 8; sp++)
            s += g_KVP[(size_t)(sp * 64 + bh) * 4096 + r];
        int d = r >> 6, e = r & 63;
        g_KVHT[(bh << 12) + (e << 6) + d] = __float2half(s);
    } else {
        int j = idx - 64 * 4096;
        if (j < 64 * 64) {
            int bh = j >> 6, d = j & 63;
            float s = 0.f;
#pragma unroll
            for (int sp = 0; sp < 8; sp++)
                s += g_KSP[(sp * 64 + bh) * 64 + d];
            g_KSUM[j] = s;
        }
    }
}

// ------------------------- K6: attn via tensor cores -------------------------
__global__ __launch_bounds__(128)
void attn_mma_kernel()
{
    __shared__ __align__(16) char sPQ[128 * 144];
    __shared__ __align__(16) char sKV[64 * 144];
    __shared__ float sDen[128];
    __shared__ float sKS[64];

    const int tid = threadIdx.x;
    const int wid = tid >> 5;
    const int lane = tid & 31;
    const int chunk = blockIdx.x;
    const int bh = blockIdx.y;
    const int b = bh >> 4, h = bh & 15;
    const size_t m0 = (size_t)b * 4096 + chunk * 128;

    const uint32_t pqb = smem_u32(sPQ);
    const uint32_t kvb = smem_u32(sKV);

    const __half* PQg = g_PHIVH + h * 64;
#pragma unroll
    for (int j = 0; j < 8; j++) {
        int o = tid + j * 128;
        int r = o >> 3, cc = o & 7;
        cp16(pqb + (uint32_t)(r * 144 + cc * 16), PQg + (m0 + r) * 3072 + cc * 8);
    }
    const __half* KVg = g_KVHT + ((size_t)bh << 12);
#pragma unroll
    for (int j = 0; j < 4; j++) {
        int o = tid + j * 128;
        int r = o >> 3, cc = o & 7;
        cp16(kvb + (uint32_t)(r * 144 + cc * 16), KVg + r * 64 + cc * 8);
    }
    asm volatile("cp.async.commit_group;" ::: "memory");
    if (tid < 64) sKS[tid] = g_KSUM[bh * 64 + tid];
    asm volatile("cp.async.wait_group 0;" ::: "memory");
    __syncthreads();

    {
        const __half* pq = (const __half*)(sPQ + tid * 144);
        float den = 0.f;
#pragma unroll 16
        for (int d = 0; d < 64; d++)
            den += __half2float(pq[d]) * sKS[d];
        sDen[tid] = 1.0f / (0.125f * den + 1e-8f);
    }

    const uint32_t aoff = pqb + (uint32_t)((wid * 32 + (lane & 15)) * 144
                                           + ((lane & 16) ? 16 : 0));
    const uint32_t boff = kvb + (uint32_t)((((lane & 16) ? 8 : 0) + (lane & 7)) * 144
                                           + ((lane & 8) ? 16 : 0));

    float acc[2][8][4];
#pragma unroll
    for (int mi = 0; mi < 2; mi++)
#pragma unroll
        for (int ni = 0; ni < 8; ni++)
#pragma unroll
            for (int q = 0; q < 4; q++) acc[mi][ni][q] = 0.f;

#pragma unroll
    for (int ksb = 0; ksb < 4; ksb++) {
        uint32_t kofs = ksb * 32;
        uint32_t af[2][4];
#pragma unroll
        for (int mi = 0; mi < 2; mi++)
            ldsm_x4(af[mi][0], af[mi][1], af[mi][2], af[mi][3],
                    aoff + mi * (16 * 144) + kofs);
        uint32_t bf[8][2];
#pragma unroll
        for (int nj = 0; nj < 4; nj++)
            ldsm_x4(bf[nj * 2][0], bf[nj * 2][1],
                    bf[nj * 2 + 1][0], bf[nj * 2 + 1][1],
                    boff + nj * (16 * 144) + kofs);
#pragma unroll
        for (int mi = 0; mi < 2; mi++)
#pragma unroll
            for (int ni = 0; ni < 8; ni++)
                mma_f16(acc[mi][ni], af[mi][0], af[mi][1], af[mi][2],
                        af[mi][3], bf[ni][0], bf[ni][1]);
    }
    __syncthreads();

    const int g = lane >> 2, tg = lane & 3;
#pragma unroll
    for (int mi = 0; mi < 2; mi++) {
        int row = wid * 32 + mi * 16 + g;
        float inv0 = sDen[row], inv1 = sDen[row + 8];
        __half* dst0 = g_ATTNH + (m0 + row) * 1024 + h * 64;
#pragma unroll
        for (int ni = 0; ni < 8; ni++) {
            int e = ni * 8 + tg * 2;
            *(half2*)(dst0 + e) =
                __floats2half2_rn(acc[mi][ni][0] * inv0, acc[mi][ni][1] * inv0);
            *(half2*)(dst0 + 8 * 1024 + e) =
                __floats2half2_rn(acc[mi][ni][2] * inv1, acc[mi][ni][3] * inv1);
        }
    }
}

// ------------------------- launch -------------------------------------------
extern "C" void kernel_launch(void* const* d_in, const int* in_sizes, int n_in,
                              void* d_out, int out_size)
{
    const float* query = (const float*)d_in[0];
    const float* Wq    = (const float*)d_in[1];
    const float* Wk    = (const float*)d_in[2];
    const float* Wv    = (const float*)d_in[3];
    const float* P     = (const float*)d_in[4];
    const float* Wo    = (const float*)d_in[5];
    const float* bo    = (const float*)d_in[6];
    float* out = (float*)d_out;

    void *p_xh, *p_wbigh, *p_worh, *p_attnh, *p_phivh;
    cudaGetSymbolAddress(&p_xh,     g_XH);
    cudaGetSymbolAddress(&p_wbigh,  g_WBIGH);
    cudaGetSymbolAddress(&p_worh,   g_WORH);
    cudaGetSymbolAddress(&p_attnh,  g_ATTNH);
    cudaGetSymbolAddress(&p_phivh,  g_PHIVH);

    cudaFuncSetAttribute((const void*)gemm_mma<__half, true, false>,
                         cudaFuncAttributeMaxDynamicSharedMemorySize, GEMM_SMEM);
    cudaFuncSetAttribute((const void*)gemm_mma<float, false, true>,
                         cudaFuncAttributeMaxDynamicSharedMemorySize, GEMM_SMEM);
    cudaFuncSetAttribute((const void*)kv_mma_kernel,
                         cudaFuncAttributeMaxDynamicSharedMemorySize, KV_SMEM);

    // fused prologue: weff + Wv copy + Wo round + query round, one launch
    prologue_kernel<<<18944, 256>>>(Wq, Wk, P, Wv, query, Wo);

    // PHIVH = relu(XH @ WBIGH^T) on first 2048 cols (fp16 out)
    gemm_mma<__half, true, false><<<dim3(24, 128), 128, GEMM_SMEM>>>(
        (const __half*)p_xh, (const __half*)p_wbigh, nullptr,
        (__half*)p_phivh, 16384, 3072, 1024, 2048);

    kv_mma_kernel<<<dim3(8, 64), 128, KV_SMEM>>>();
    kv_reduce_kernel<<<1040, 256>>>();
    attn_mma_kernel<<<dim3(32, 64), 128>>>();   // writes fp16 ATTN

    // out = ATTNH @ WORH^T + bo (fp32 out)
    gemm_mma<float, false, true><<<dim3(8, 128), 128, GEMM_SMEM>>>(
        (const __half*)p_attnh, (const __half*)p_worh, bo, out,
        16384, 1024, 1024, 0);
}

// round 13
// speedup vs baseline: 1.0306x; 1.0013x over previous
#include <cuda_runtime.h>
#include <cuda_fp16.h>
#include <cstdint>

// ---------------------------------------------------------------------------
// FastAttention — linear attention with ReLU feature maps.
// Big GEMMs: fp16 mma m16n8k16, CTA 128x128x64, 128 thr (warp 64x64),
// 3-stage cp.async (144B rows), 2 CTAs/SM. kv/attn on tensor cores.
// This round: SMEM-staged coalesced epilogue for fp16-output GEMM
// (full 128B store lines instead of 16B-per-4-lane partial sectors).
// ---------------------------------------------------------------------------

// ------------------------- device scratch (no allocs) ----------------------
__device__ __align__(16) __half g_XH[(size_t)16384 * 1024];
__device__ __align__(16) __half g_WBIGH[(size_t)3072 * 1024];
__device__ __align__(16) __half g_WORH[(size_t)1024 * 1024];
__device__ __align__(16) __half g_ATTNH[(size_t)16384 * 1024];
__device__ __align__(16) __half g_PHIVH[(size_t)16384 * 3072];
__device__ __align__(16) __half g_KVHT[64 * 64 * 64];   // [bh][e][d] fp16
__device__ float g_KSUM[64 * 64];
__device__ float g_KVP[8 * 64 * 64 * 64];
__device__ float g_KSP[8 * 64 * 64];

// ------------------------- helpers ------------------------------------------
__device__ __forceinline__ uint32_t smem_u32(const void* p) {
    uint32_t a;
    asm("{ .reg .u64 t; cvta.to.shared.u64 t, %1; cvt.u32.u64 %0, t; }"
        : "=r"(a) : "l"(p));
    return a;
}
__device__ __forceinline__ void cp16(uint32_t dst, const void* src) {
    asm volatile("cp.async.cg.shared.global [%0], [%1], 16;" :: "r"(dst), "l"(src));
}
__device__ __forceinline__ void ldsm_x4(uint32_t& r0, uint32_t& r1,
                                        uint32_t& r2, uint32_t& r3, uint32_t a) {
    asm volatile("ldmatrix.sync.aligned.m8n8.x4.shared.b16 {%0,%1,%2,%3}, [%4];"
                 : "=r"(r0), "=r"(r1), "=r"(r2), "=r"(r3) : "r"(a));
}
__device__ __forceinline__ void ldsm_x4_t(uint32_t& r0, uint32_t& r1,
                                          uint32_t& r2, uint32_t& r3, uint32_t a) {
    asm volatile("ldmatrix.sync.aligned.m8n8.x4.trans.shared.b16 {%0,%1,%2,%3}, [%4];"
                 : "=r"(r0), "=r"(r1), "=r"(r2), "=r"(r3) : "r"(a));
}
__device__ __forceinline__ void mma_f16(float* c, uint32_t a0, uint32_t a1,
                                        uint32_t a2, uint32_t a3,
                                        uint32_t b0, uint32_t b1) {
    asm volatile(
        "mma.sync.aligned.m16n8k16.row.col.f32.f16.f16.f32 "
        "{%0,%1,%2,%3}, {%4,%5,%6,%7}, {%8,%9}, {%0,%1,%2,%3};"
        : "+f"(c[0]), "+f"(c[1]), "+f"(c[2]), "+f"(c[3])
        : "r"(a0), "r"(a1), "r"(a2), "r"(a3), "r"(b0), "r"(b1));
}
__device__ __forceinline__ void sts32(uint32_t addr, uint32_t v) {
    asm volatile("st.shared.b32 [%0], %1;" :: "r"(addr), "r"(v) : "memory");
}
__device__ __forceinline__ void lds128(uint32_t addr, uint4& v) {
    asm volatile("ld.shared.v4.u32 {%0,%1,%2,%3}, [%4];"
                 : "=r"(v.x), "=r"(v.y), "=r"(v.z), "=r"(v.w) : "r"(addr));
}

// ------------------------- fused prologue ------------------------------------
// blocks [0,512):      Weff fold (Wq/Wk x per-head P) -> WBIGH fp16
// blocks [512,1536):   Wv rows -> WBIGH fp16
// blocks [1536,2560):  Wo -> WORH fp16
// blocks [2560,18944): query -> XH fp16
__global__ __launch_bounds__(256)
void prologue_kernel(const float* __restrict__ Wq,
                     const float* __restrict__ Wk,
                     const float* __restrict__ P,
                     const float* __restrict__ Wv,
                     const float* __restrict__ query,
                     const float* __restrict__ Wo)
{
    int bid = blockIdx.x;
    int tid = threadIdx.x;

    if (bid < 512) {
        int which = bid >> 8;
        int rem   = bid & 255;
        int h     = rem >> 4;
        int chunk = rem & 15;
        const float* W = which ? Wk : Wq;

        __shared__ float Psh[64][64];
        __shared__ float Wsh[64][64];
#pragma unroll
        for (int i = 0; i < 4; i++) {
            int f = tid + i * 256;
            int e = f >> 4, c4 = (f & 15) << 2;
            *(float4*)&Psh[e][c4] = *(const float4*)(P + (size_t)h * 4096 + f * 4);
            *(float4*)&Wsh[e][c4] =
                *(const float4*)(W + (size_t)(h * 64 + e) * 1024 + chunk * 64 + c4);
        }
        __syncthreads();

        int dp = tid & 63;
        int dg = tid >> 6;
        float acc[16];
#pragma unroll
        for (int j = 0; j < 16; j++) acc[j] = 0.f;
#pragma unroll 4
        for (int e = 0; e < 64; e++) {
            float p = Psh[e][dp];
#pragma unroll
            for (int j = 0; j < 16; j++)
                acc[j] += p * Wsh[e][dg * 16 + j];
        }
        __half* dst = g_WBIGH + (size_t)(which * 1024 + h * 64 + dp) * 1024
                              + chunk * 64 + dg * 16;
#pragma unroll
        for (int j = 0; j < 16; j += 2)
            *(half2*)(dst + j) = __floats2half2_rn(acc[j], acc[j + 1]);
    } else if (bid < 1536) {
        int row = bid - 512;
        float4 v = *(const float4*)(Wv + (size_t)row * 1024 + tid * 4);
        __half* dst = g_WBIGH + (size_t)(2048 + row) * 1024 + tid * 4;
        *(half2*)(dst)     = __floats2half2_rn(v.x, v.y);
        *(half2*)(dst + 2) = __floats2half2_rn(v.z, v.w);
    } else if (bid < 2560) {
        size_t i = ((size_t)(bid - 1536) * 256 + tid) * 4;
        float4 v = *(const float4*)(Wo + i);
        *(half2*)(g_WORH + i)     = __floats2half2_rn(v.x, v.y);
        *(half2*)(g_WORH + i + 2) = __floats2half2_rn(v.z, v.w);
    } else {
        size_t i = ((size_t)(bid - 2560) * 256 + tid) * 4;
        float4 v = *(const float4*)(query + i);
        *(half2*)(g_XH + i)     = __floats2half2_rn(v.x, v.y);
        *(half2*)(g_XH + i + 2) = __floats2half2_rn(v.z, v.w);
    }
}

// ------------------------- fp16 mma GEMM (k64, staged epilogue) -------------
constexpr int HROW_B   = 144;                      // 128B data + 16B pad
constexpr int H_TILE_B = 128 * HROW_B;             // 18432 per A/B tile
constexpr int H_STAGE  = 2 * H_TILE_B;             // 36864
constexpr int H_STAGES = 3;
constexpr int GEMM_SMEM = H_STAGES * H_STAGE;      // 110592 B

template<typename OutT, bool RELU, bool BIAS>
__global__ __launch_bounds__(128, 2)
void gemm_mma(const __half* __restrict__ A, const __half* __restrict__ Bm,
              const float* __restrict__ bias, OutT* __restrict__ C,
              int M, int N, int K, int relu_cols)
{
    extern __shared__ char smem[];
    const int tid = threadIdx.x;
    const int m0 = blockIdx.y * 128;
    const int n0 = blockIdx.x * 128;
    const int KT = K >> 6;                         // chunks of 64 halfs

    const uint32_t smem_base = smem_u32(smem);

    auto load_stage = [&](int kt, int buf) {
        uint32_t ab = smem_base + buf * H_STAGE;
        uint32_t bb = ab + H_TILE_B;
        const __half* Asrc = A + (size_t)m0 * K + kt * 64;
        const __half* Bsrc = Bm + (size_t)n0 * K + kt * 64;
#pragma unroll
        for (int j = 0; j < 8; j++) {              // 1024 cp16 per tile
            int o = tid + j * 128;
            int r = o >> 3, cc = o & 7;
            cp16(ab + (uint32_t)(r * HROW_B + cc * 16),
                 Asrc + (size_t)r * K + cc * 8);
            cp16(bb + (uint32_t)(r * HROW_B + cc * 16),
                 Bsrc + (size_t)r * K + cc * 8);
        }
    };

    const int wid  = tid >> 5;
    const int lane = tid & 31;
    const int wm = wid & 1;
    const int wn = wid >> 1;
    const int g  = lane >> 2;
    const int tg = lane & 3;

    const uint32_t aoff = (uint32_t)((wm * 64 + (lane & 15)) * HROW_B
                                     + ((lane & 16) ? 16 : 0));
    const uint32_t boff = (uint32_t)((wn * 64 + ((lane & 16) ? 8 : 0)
                                      + (lane & 7)) * HROW_B
                                     + ((lane & 8) ? 16 : 0));

    float acc[4][8][4];
#pragma unroll
    for (int mi = 0; mi < 4; mi++)
#pragma unroll
        for (int ni = 0; ni < 8; ni++)
#pragma unroll
            for (int q = 0; q < 4; q++) acc[mi][ni][q] = 0.f;

    uint32_t fa[2][4][4], fb[2][8][2];

    auto load_frags = [&](uint32_t As, uint32_t Bs, int ks, int buf) {
        uint32_t kofs = (uint32_t)ks * 32;
#pragma unroll
        for (int mi = 0; mi < 4; mi++)
            ldsm_x4(fa[buf][mi][0], fa[buf][mi][1], fa[buf][mi][2],
                    fa[buf][mi][3], As + aoff + mi * (16 * HROW_B) + kofs);
#pragma unroll
        for (int nj = 0; nj < 4; nj++)
            ldsm_x4(fb[buf][nj * 2][0], fb[buf][nj * 2][1],
                    fb[buf][nj * 2 + 1][0], fb[buf][nj * 2 + 1][1],
                    Bs + boff + nj * (16 * HROW_B) + kofs);
    };

    load_stage(0, 0);
    asm volatile("cp.async.commit_group;" ::: "memory");
    load_stage(1, 1);
    asm volatile("cp.async.commit_group;" ::: "memory");

    for (int kt = 0; kt < KT; kt++) {
        asm volatile("cp.async.wait_group 1;" ::: "memory");
        __syncthreads();

        if (kt + 2 < KT) load_stage(kt + 2, (kt + 2) % 3);
        asm volatile("cp.async.commit_group;" ::: "memory");

        uint32_t As = smem_base + (kt % 3) * H_STAGE;
        uint32_t Bs = As + H_TILE_B;

        load_frags(As, Bs, 0, 0);
#pragma unroll
        for (int ks = 0; ks < 4; ks++) {
            int cur = ks & 1;
            if (ks < 3) load_frags(As, Bs, ks + 1, cur ^ 1);
#pragma unroll
            for (int mi = 0; mi < 4; mi++)
#pragma unroll
                for (int ni = 0; ni < 8; ni++)
                    mma_f16(acc[mi][ni],
                            fa[cur][mi][0], fa[cur][mi][1],
                            fa[cur][mi][2], fa[cur][mi][3],
                            fb[cur][ni][0], fb[cur][ni][1]);
        }
    }

    if constexpr (sizeof(OutT) == 2) {
        // ---- SMEM-staged coalesced fp16 epilogue ----
        __syncthreads();                           // retire mainloop SMEM reads
        // per-warp slab: 16 rows x 72 halfs (144B stride) = 2304 B
        const uint32_t eb = smem_base + (uint32_t)wid * (16 * 144);
#pragma unroll
        for (int mi = 0; mi < 4; mi++) {
#pragma unroll
            for (int ni = 0; ni < 8; ni++) {
                int col = n0 + wn * 64 + ni * 8 + tg * 2;
                float2 v0 = make_float2(acc[mi][ni][0], acc[mi][ni][1]);
                float2 v1 = make_float2(acc[mi][ni][2], acc[mi][ni][3]);
                if (BIAS) {
                    float2 b2 = *(const float2*)(bias + col);
                    v0.x += b2.x; v0.y += b2.y;
                    v1.x += b2.x; v1.y += b2.y;
                }
                if (RELU && col < relu_cols) {
                    v0.x = fmaxf(v0.x, 0.f); v0.y = fmaxf(v0.y, 0.f);
                    v1.x = fmaxf(v1.x, 0.f); v1.y = fmaxf(v1.y, 0.f);
                }
                uint32_t cofs = (uint32_t)((ni * 8 + tg * 2) * 2);
                half2 h0 = __floats2half2_rn(v0.x, v0.y);
                half2 h1 = __floats2half2_rn(v1.x, v1.y);
                sts32(eb + (uint32_t)(g * 144) + cofs,
                      *(uint32_t*)&h0);
                sts32(eb + (uint32_t)((g + 8) * 144) + cofs,
                      *(uint32_t*)&h1);
            }
            __syncwarp();
            // flush: 16 rows x 128B, 16B per lane, 4 passes
#pragma unroll
            for (int p = 0; p < 4; p++) {
                int row = p * 4 + (lane >> 3);
                int cc  = lane & 7;
                uint4 val;
                lds128(eb + (uint32_t)(row * 144 + cc * 16), val);
                int grow = m0 + wm * 64 + mi * 16 + row;
                *(uint4*)((__half*)C + (size_t)grow * N
                          + n0 + wn * 64 + cc * 8) = val;
            }
            __syncwarp();
        }
    } else {
        // ---- direct fp32 epilogue (already sector-aligned) ----
#pragma unroll
        for (int mi = 0; mi < 4; mi++) {
            int row0 = m0 + wm * 64 + mi * 16 + g;
#pragma unroll
            for (int ni = 0; ni < 8; ni++) {
                int col = n0 + wn * 64 + ni * 8 + tg * 2;
                float2 v0 = make_float2(acc[mi][ni][0], acc[mi][ni][1]);
                float2 v1 = make_float2(acc[mi][ni][2], acc[mi][ni][3]);
                if (BIAS) {
                    float2 b2 = *(const float2*)(bias + col);
                    v0.x += b2.x; v0.y += b2.y;
                    v1.x += b2.x; v1.y += b2.y;
                }
                if (RELU && col < relu_cols) {
                    v0.x = fmaxf(v0.x, 0.f); v0.y = fmaxf(v0.y, 0.f);
                    v1.x = fmaxf(v1.x, 0.f); v1.y = fmaxf(v1.y, 0.f);
                }
                *(float2*)((float*)C + (size_t)row0 * N + col) = v0;
                *(float2*)((float*)C + (size_t)(row0 + 8) * N + col) = v1;
            }
        }
    }
}

// ------------------------- K4: kv + ksum via tensor cores (8 splits) ---------
constexpr int KVROW_B   = 144;
constexpr int KV_TILE_B = 64 * KVROW_B;            // 9216
constexpr int KV_STAGE  = 2 * KV_TILE_B;           // 18432
constexpr int KV_SMEM   = 3 * KV_STAGE;            // 55296

__global__ __launch_bounds__(128)
void kv_mma_kernel()
{
    extern __shared__ char skv[];
    const uint32_t sb = smem_u32(skv);
    const int tid = threadIdx.x;
    const int wid = tid >> 5;
    const int lane = tid & 31;
    const int split = blockIdx.x;
    const int bh = blockIdx.y;
    const int b = bh >> 4, h = bh & 15;
    const size_t base_row = (size_t)b * 4096 + split * 512;
    const __half* PKg = g_PHIVH + 1024 + h * 64;
    const __half* VVg = g_PHIVH + 2048 + h * 64;

    auto load_chunk = [&](int c, int buf) {
        uint32_t pb = sb + buf * KV_STAGE;
        uint32_t vb = pb + KV_TILE_B;
        size_t row0 = base_row + c * 64;
#pragma unroll
        for (int j = 0; j < 4; j++) {
            int o = tid + j * 128;
            int r = o >> 3, cc = o & 7;
            size_t off = (row0 + r) * 3072 + cc * 8;
            cp16(pb + (uint32_t)(r * KVROW_B + cc * 16), PKg + off);
            cp16(vb + (uint32_t)(r * KVROW_B + cc * 16), VVg + off);
        }
    };

    const uint32_t a_off = (uint32_t)((((lane & 16) ? 8 : 0) + (lane & 7)) * KVROW_B
                                      + wid * 32 + ((lane & 8) ? 16 : 0));
    const uint32_t b_off = (uint32_t)((((lane & 8) ? 8 : 0) + (lane & 7)) * KVROW_B
                                      + ((lane & 16) ? 16 : 0));

    float acc[8][4];
#pragma unroll
    for (int ni = 0; ni < 8; ni++)
#pragma unroll
        for (int q = 0; q < 4; q++) acc[ni][q] = 0.f;
    float ks = 0.f;

    load_chunk(0, 0);
    asm volatile("cp.async.commit_group;" ::: "memory");
    load_chunk(1, 1);
    asm volatile("cp.async.commit_group;" ::: "memory");

    for (int c = 0; c < 8; c++) {
        asm volatile("cp.async.wait_group 1;" ::: "memory");
        __syncthreads();
        if (c + 2 < 8) load_chunk(c + 2, (c + 2) % 3);
        asm volatile("cp.async.commit_group;" ::: "memory");

        uint32_t pb = sb + (c % 3) * KV_STAGE;
        uint32_t vb = pb + KV_TILE_B;

        if (tid < 64) {
            const __half* pk = (const __half*)(skv + (c % 3) * KV_STAGE);
#pragma unroll 8
            for (int n = 0; n < 64; n++)
                ks += __half2float(*(const __half*)((const char*)pk
                                                    + n * KVROW_B + tid * 2));
        }

#pragma unroll
        for (int kk = 0; kk < 4; kk++) {
            uint32_t a0, a1, a2, a3;
            ldsm_x4_t(a0, a1, a2, a3, pb + kk * (16 * KVROW_B) + a_off);
#pragma unroll
            for (int eb = 0; eb < 4; eb++) {
                uint32_t r0, r1, r2, r3;
                ldsm_x4_t(r0, r1, r2, r3,
                          vb + kk * (16 * KVROW_B) + b_off + eb * 32);
                mma_f16(acc[eb * 2],     a0, a1, a2, a3, r0, r1);
                mma_f16(acc[eb * 2 + 1], a0, a1, a2, a3, r2, r3);
            }
        }
    }

    float* dst = g_KVP + (size_t)(split * 64 + bh) * 4096;
    int g = lane >> 2, tg = lane & 3;
#pragma unroll
    for (int ni = 0; ni < 8; ni++) {
        int e = ni * 8 + tg * 2;
        int d0 = wid * 16 + g;
        dst[d0 * 64 + e]           = acc[ni][0];
        dst[d0 * 64 + e + 1]       = acc[ni][1];
        dst[(d0 + 8) * 64 + e]     = acc[ni][2];
        dst[(d0 + 8) * 64 + e + 1] = acc[ni][3];
    }
    if (tid < 64) g_KSP[(split * 64 + bh) * 64 + tid] = ks;
}

// ------------------------- K5: reduction -> fp16 transposed kv ---------------
__global__ __launch_bounds__(256)
void kv_reduce_kernel()
{
    int idx = blockIdx.x * 256 + threadIdx.x;
    if (idx < 64 * 4096) {
        int bh = idx >> 12, r = idx & 4095;
        float s = 0.f;
#pragma unroll
        for (int sp = 0; sp < 8; sp++)
            s += g_KVP[(size_t)(sp * 64 + bh) * 4096 + r];
        int d = r >> 6, e = r & 63;
        g_KVHT[(bh << 12) + (e << 6) + d] = __float2half(s);
    } else {
        int j = idx - 64 * 4096;
        if (j < 64 * 64) {
            int bh = j >> 6, d = j & 63;
            float s = 0.f;
#pragma unroll
            for (int sp = 0; sp < 8; sp++)
                s += g_KSP[(sp * 64 + bh) * 64 + d];
            g_KSUM[j] = s;
        }
    }
}

// ------------------------- K6: attn via tensor cores -------------------------
__global__ __launch_bounds__(128)
void attn_mma_kernel()
{
    __shared__ __align__(16) char sPQ[128 * 144];
    __shared__ __align__(16) char sKV[64 * 144];
    __shared__ float sDen[128];
    __shared__ float sKS[64];

    const int tid = threadIdx.x;
    const int wid = tid >> 5;
    const int lane = tid & 31;
    const int chunk = blockIdx.x;
    const int bh = blockIdx.y;
    const int b = bh >> 4, h = bh & 15;
    const size_t m0 = (size_t)b * 4096 + chunk * 128;

    const uint32_t pqb = smem_u32(sPQ);
    const uint32_t kvb = smem_u32(sKV);

    const __half* PQg = g_PHIVH + h * 64;
#pragma unroll
    for (int j = 0; j < 8; j++) {
        int o = tid + j * 128;
        int r = o >> 3, cc = o & 7;
        cp16(pqb + (uint32_t)(r * 144 + cc * 16), PQg + (m0 + r) * 3072 + cc * 8);
    }
    const __half* KVg = g_KVHT + ((size_t)bh << 12);
#pragma unroll
    for (int j = 0; j < 4; j++) {
        int o = tid + j * 128;
        int r = o >> 3, cc = o & 7;
        cp16(kvb + (uint32_t)(r * 144 + cc * 16), KVg + r * 64 + cc * 8);
    }
    asm volatile("cp.async.commit_group;" ::: "memory");
    if (tid < 64) sKS[tid] = g_KSUM[bh * 64 + tid];
    asm volatile("cp.async.wait_group 0;" ::: "memory");
    __syncthreads();

    {
        const __half* pq = (const __half*)(sPQ + tid * 144);
        float den = 0.f;
#pragma unroll 16
        for (int d = 0; d < 64; d++)
            den += __half2float(pq[d]) * sKS[d];
        sDen[tid] = 1.0f / (0.125f * den + 1e-8f);
    }

    const uint32_t aoff = pqb + (uint32_t)((wid * 32 + (lane & 15)) * 144
                                           + ((lane & 16) ? 16 : 0));
    const uint32_t boff = kvb + (uint32_t)((((lane & 16) ? 8 : 0) + (lane & 7)) * 144
                                           + ((lane & 8) ? 16 : 0));

    float acc[2][8][4];
#pragma unroll
    for (int mi = 0; mi < 2; mi++)
#pragma unroll
        for (int ni = 0; ni < 8; ni++)
#pragma unroll
            for (int q = 0; q < 4; q++) acc[mi][ni][q] = 0.f;

#pragma unroll
    for (int ksb = 0; ksb < 4; ksb++) {
        uint32_t kofs = ksb * 32;
        uint32_t af[2][4];
#pragma unroll
        for (int mi = 0; mi < 2; mi++)
            ldsm_x4(af[mi][0], af[mi][1], af[mi][2], af[mi][3],
                    aoff + mi * (16 * 144) + kofs);
        uint32_t bf[8][2];
#pragma unroll
        for (int nj = 0; nj < 4; nj++)
            ldsm_x4(bf[nj * 2][0], bf[nj * 2][1],
                    bf[nj * 2 + 1][0], bf[nj * 2 + 1][1],
                    boff + nj * (16 * 144) + kofs);
#pragma unroll
        for (int mi = 0; mi < 2; mi++)
#pragma unroll
            for (int ni = 0; ni < 8; ni++)
                mma_f16(acc[mi][ni], af[mi][0], af[mi][1], af[mi][2],
                        af[mi][3], bf[ni][0], bf[ni][1]);
    }
    __syncthreads();

    const int g = lane >> 2, tg = lane & 3;
#pragma unroll
    for (int mi = 0; mi < 2; mi++) {
        int row = wid * 32 + mi * 16 + g;
        float inv0 = sDen[row], inv1 = sDen[row + 8];
        __half* dst0 = g_ATTNH + (m0 + row) * 1024 + h * 64;
#pragma unroll
        for (int ni = 0; ni < 8; ni++) {
            int e = ni * 8 + tg * 2;
            *(half2*)(dst0 + e) =
                __floats2half2_rn(acc[mi][ni][0] * inv0, acc[mi][ni][1] * inv0);
            *(half2*)(dst0 + 8 * 1024 + e) =
                __floats2half2_rn(acc[mi][ni][2] * inv1, acc[mi][ni][3] * inv1);
        }
    }
}

// ------------------------- launch -------------------------------------------
extern "C" void kernel_launch(void* const* d_in, const int* in_sizes, int n_in,
                              void* d_out, int out_size)
{
    const float* query = (const float*)d_in[0];
    const float* Wq    = (const float*)d_in[1];
    const float* Wk    = (const float*)d_in[2];
    const float* Wv    = (const float*)d_in[3];
    const float* P     = (const float*)d_in[4];
    const float* Wo    = (const float*)d_in[5];
    const float* bo    = (const float*)d_in[6];
    float* out = (float*)d_out;

    void *p_xh, *p_wbigh, *p_worh, *p_attnh, *p_phivh;
    cudaGetSymbolAddress(&p_xh,     g_XH);
    cudaGetSymbolAddress(&p_wbigh,  g_WBIGH);
    cudaGetSymbolAddress(&p_worh,   g_WORH);
    cudaGetSymbolAddress(&p_attnh,  g_ATTNH);
    cudaGetSymbolAddress(&p_phivh,  g_PHIVH);

    cudaFuncSetAttribute((const void*)gemm_mma<__half, true, false>,
                         cudaFuncAttributeMaxDynamicSharedMemorySize, GEMM_SMEM);
    cudaFuncSetAttribute((const void*)gemm_mma<float, false, true>,
                         cudaFuncAttributeMaxDynamicSharedMemorySize, GEMM_SMEM);
    cudaFuncSetAttribute((const void*)kv_mma_kernel,
                         cudaFuncAttributeMaxDynamicSharedMemorySize, KV_SMEM);

    // fused prologue: weff + Wv copy + Wo round + query round, one launch
    prologue_kernel<<<18944, 256>>>(Wq, Wk, P, Wv, query, Wo);

    // PHIVH = relu(XH @ WBIGH^T) on first 2048 cols (fp16 out)
    gemm_mma<__half, true, false><<<dim3(24, 128), 128, GEMM_SMEM>>>(
        (const __half*)p_xh, (const __half*)p_wbigh, nullptr,
        (__half*)p_phivh, 16384, 3072, 1024, 2048);

    kv_mma_kernel<<<dim3(8, 64), 128, KV_SMEM>>>();
    kv_reduce_kernel<<<1040, 256>>>();
    attn_mma_kernel<<<dim3(32, 64), 128>>>();   // writes fp16 ATTN

    // out = ATTNH @ WORH^T + bo (fp32 out)
    gemm_mma<float, false, true><<<dim3(8, 128), 128, GEMM_SMEM>>>(
        (const __half*)p_attnh, (const __half*)p_worh, bo, out,
        16384, 1024, 1024, 0);
}

// round 14
// speedup vs baseline: 1.0447x; 1.0136x over previous
#include <cuda_runtime.h>
#include <cuda_fp16.h>
#include <cstdint>

// ---------------------------------------------------------------------------
// FastAttention — linear attention with ReLU feature maps.
// Big GEMMs: fp16 mma m16n8k16, CTA 128x128x64, 128 thr (warp 64x64),
// 3-stage cp.async (144B rows), 2 CTAs/SM. kv/attn on tensor cores.
// This round: vectorized prologue stores (16B), kv kept [d][e] with a
// float4-vectorized reduce, attn reads kv via ldmatrix.trans.
// ---------------------------------------------------------------------------

// ------------------------- device scratch (no allocs) ----------------------
__device__ __align__(16) __half g_XH[(size_t)16384 * 1024];
__device__ __align__(16) __half g_WBIGH[(size_t)3072 * 1024];
__device__ __align__(16) __half g_WORH[(size_t)1024 * 1024];
__device__ __align__(16) __half g_ATTNH[(size_t)16384 * 1024];
__device__ __align__(16) __half g_PHIVH[(size_t)16384 * 3072];
__device__ __align__(16) __half g_KVH[64 * 64 * 64];    // [bh][d][e] fp16
__device__ float g_KSUM[64 * 64];
__device__ float g_KVP[8 * 64 * 64 * 64];
__device__ float g_KSP[8 * 64 * 64];

// ------------------------- helpers ------------------------------------------
__device__ __forceinline__ uint32_t smem_u32(const void* p) {
    uint32_t a;
    asm("{ .reg .u64 t; cvta.to.shared.u64 t, %1; cvt.u32.u64 %0, t; }"
        : "=r"(a) : "l"(p));
    return a;
}
__device__ __forceinline__ void cp16(uint32_t dst, const void* src) {
    asm volatile("cp.async.cg.shared.global [%0], [%1], 16;" :: "r"(dst), "l"(src));
}
__device__ __forceinline__ void ldsm_x4(uint32_t& r0, uint32_t& r1,
                                        uint32_t& r2, uint32_t& r3, uint32_t a) {
    asm volatile("ldmatrix.sync.aligned.m8n8.x4.shared.b16 {%0,%1,%2,%3}, [%4];"
                 : "=r"(r0), "=r"(r1), "=r"(r2), "=r"(r3) : "r"(a));
}
__device__ __forceinline__ void ldsm_x4_t(uint32_t& r0, uint32_t& r1,
                                          uint32_t& r2, uint32_t& r3, uint32_t a) {
    asm volatile("ldmatrix.sync.aligned.m8n8.x4.trans.shared.b16 {%0,%1,%2,%3}, [%4];"
                 : "=r"(r0), "=r"(r1), "=r"(r2), "=r"(r3) : "r"(a));
}
__device__ __forceinline__ void mma_f16(float* c, uint32_t a0, uint32_t a1,
                                        uint32_t a2, uint32_t a3,
                                        uint32_t b0, uint32_t b1) {
    asm volatile(
        "mma.sync.aligned.m16n8k16.row.col.f32.f16.f16.f32 "
        "{%0,%1,%2,%3}, {%4,%5,%6,%7}, {%8,%9}, {%0,%1,%2,%3};"
        : "+f"(c[0]), "+f"(c[1]), "+f"(c[2]), "+f"(c[3])
        : "r"(a0), "r"(a1), "r"(a2), "r"(a3), "r"(b0), "r"(b1));
}

// ------------------------- fused prologue ------------------------------------
// blocks [0,512):      Weff fold (Wq/Wk x per-head P) -> WBIGH fp16
// blocks [512,1536):   Wv rows -> WBIGH fp16
// blocks [1536,2048):  Wo -> WORH fp16      (8 floats/thread, 16B stores)
// blocks [2048,10240): query -> XH fp16     (8 floats/thread, 16B stores)
__global__ __launch_bounds__(256)
void prologue_kernel(const float* __restrict__ Wq,
                     const float* __restrict__ Wk,
                     const float* __restrict__ P,
                     const float* __restrict__ Wv,
                     const float* __restrict__ query,
                     const float* __restrict__ Wo)
{
    int bid = blockIdx.x;
    int tid = threadIdx.x;

    if (bid < 512) {
        int which = bid >> 8;
        int rem   = bid & 255;
        int h     = rem >> 4;
        int chunk = rem & 15;
        const float* W = which ? Wk : Wq;

        __shared__ float Psh[64][64];
        __shared__ float Wsh[64][64];
#pragma unroll
        for (int i = 0; i < 4; i++) {
            int f = tid + i * 256;
            int e = f >> 4, c4 = (f & 15) << 2;
            *(float4*)&Psh[e][c4] = *(const float4*)(P + (size_t)h * 4096 + f * 4);
            *(float4*)&Wsh[e][c4] =
                *(const float4*)(W + (size_t)(h * 64 + e) * 1024 + chunk * 64 + c4);
        }
        __syncthreads();

        int dp = tid & 63;
        int dg = tid >> 6;
        float acc[16];
#pragma unroll
        for (int j = 0; j < 16; j++) acc[j] = 0.f;
#pragma unroll 4
        for (int e = 0; e < 64; e++) {
            float p = Psh[e][dp];
#pragma unroll
            for (int j = 0; j < 16; j++)
                acc[j] += p * Wsh[e][dg * 16 + j];
        }
        __half* dst = g_WBIGH + (size_t)(which * 1024 + h * 64 + dp) * 1024
                              + chunk * 64 + dg * 16;
#pragma unroll
        for (int j = 0; j < 16; j += 8) {
            half2 h0 = __floats2half2_rn(acc[j],     acc[j + 1]);
            half2 h1 = __floats2half2_rn(acc[j + 2], acc[j + 3]);
            half2 h2 = __floats2half2_rn(acc[j + 4], acc[j + 5]);
            half2 h3 = __floats2half2_rn(acc[j + 6], acc[j + 7]);
            uint4 u = make_uint4(*(uint32_t*)&h0, *(uint32_t*)&h1,
                                 *(uint32_t*)&h2, *(uint32_t*)&h3);
            *(uint4*)(dst + j) = u;
        }
    } else if (bid < 1536) {
        int row = bid - 512;
        float4 v = *(const float4*)(Wv + (size_t)row * 1024 + tid * 4);
        __half* dst = g_WBIGH + (size_t)(2048 + row) * 1024 + tid * 4;
        half2 h0 = __floats2half2_rn(v.x, v.y);
        half2 h1 = __floats2half2_rn(v.z, v.w);
        uint2 u = make_uint2(*(uint32_t*)&h0, *(uint32_t*)&h1);
        *(uint2*)(dst) = u;
    } else if (bid < 2048) {
        size_t i = ((size_t)(bid - 1536) * 256 + tid) * 8;
        float4 v0 = *(const float4*)(Wo + i);
        float4 v1 = *(const float4*)(Wo + i + 4);
        half2 h0 = __floats2half2_rn(v0.x, v0.y);
        half2 h1 = __floats2half2_rn(v0.z, v0.w);
        half2 h2 = __floats2half2_rn(v1.x, v1.y);
        half2 h3 = __floats2half2_rn(v1.z, v1.w);
        uint4 u = make_uint4(*(uint32_t*)&h0, *(uint32_t*)&h1,
                             *(uint32_t*)&h2, *(uint32_t*)&h3);
        *(uint4*)(g_WORH + i) = u;
    } else {
        size_t i = ((size_t)(bid - 2048) * 256 + tid) * 8;
        float4 v0 = *(const float4*)(query + i);
        float4 v1 = *(const float4*)(query + i + 4);
        half2 h0 = __floats2half2_rn(v0.x, v0.y);
        half2 h1 = __floats2half2_rn(v0.z, v0.w);
        half2 h2 = __floats2half2_rn(v1.x, v1.y);
        half2 h3 = __floats2half2_rn(v1.z, v1.w);
        uint4 u = make_uint4(*(uint32_t*)&h0, *(uint32_t*)&h1,
                             *(uint32_t*)&h2, *(uint32_t*)&h3);
        *(uint4*)(g_XH + i) = u;
    }
}

// ------------------------- fp16 mma GEMM (k64) ------------------------------
constexpr int HROW_B   = 144;                      // 128B data + 16B pad
constexpr int H_TILE_B = 128 * HROW_B;             // 18432 per A/B tile
constexpr int H_STAGE  = 2 * H_TILE_B;             // 36864
constexpr int H_STAGES = 3;
constexpr int GEMM_SMEM = H_STAGES * H_STAGE;      // 110592 B

template<typename OutT, bool RELU, bool BIAS>
__global__ __launch_bounds__(128, 2)
void gemm_mma(const __half* __restrict__ A, const __half* __restrict__ Bm,
              const float* __restrict__ bias, OutT* __restrict__ C,
              int M, int N, int K, int relu_cols)
{
    extern __shared__ char smem[];
    const int tid = threadIdx.x;
    const int m0 = blockIdx.y * 128;
    const int n0 = blockIdx.x * 128;
    const int KT = K >> 6;                         // chunks of 64 halfs

    const uint32_t smem_base = smem_u32(smem);

    auto load_stage = [&](int kt, int buf) {
        uint32_t ab = smem_base + buf * H_STAGE;
        uint32_t bb = ab + H_TILE_B;
        const __half* Asrc = A + (size_t)m0 * K + kt * 64;
        const __half* Bsrc = Bm + (size_t)n0 * K + kt * 64;
#pragma unroll
        for (int j = 0; j < 8; j++) {              // 1024 cp16 per tile
            int o = tid + j * 128;
            int r = o >> 3, cc = o & 7;
            cp16(ab + (uint32_t)(r * HROW_B + cc * 16),
                 Asrc + (size_t)r * K + cc * 8);
            cp16(bb + (uint32_t)(r * HROW_B + cc * 16),
                 Bsrc + (size_t)r * K + cc * 8);
        }
    };

    const int wid  = tid >> 5;
    const int lane = tid & 31;
    const int wm = wid & 1;
    const int wn = wid >> 1;
    const int g  = lane >> 2;
    const int tg = lane & 3;

    const uint32_t aoff = (uint32_t)((wm * 64 + (lane & 15)) * HROW_B
                                     + ((lane & 16) ? 16 : 0));
    const uint32_t boff = (uint32_t)((wn * 64 + ((lane & 16) ? 8 : 0)
                                      + (lane & 7)) * HROW_B
                                     + ((lane & 8) ? 16 : 0));

    float acc[4][8][4];
#pragma unroll
    for (int mi = 0; mi < 4; mi++)
#pragma unroll
        for (int ni = 0; ni < 8; ni++)
#pragma unroll
            for (int q = 0; q < 4; q++) acc[mi][ni][q] = 0.f;

    uint32_t fa[2][4][4], fb[2][8][2];

    auto load_frags = [&](uint32_t As, uint32_t Bs, int ks, int buf) {
        uint32_t kofs = (uint32_t)ks * 32;
#pragma unroll
        for (int mi = 0; mi < 4; mi++)
            ldsm_x4(fa[buf][mi][0], fa[buf][mi][1], fa[buf][mi][2],
                    fa[buf][mi][3], As + aoff + mi * (16 * HROW_B) + kofs);
#pragma unroll
        for (int nj = 0; nj < 4; nj++)
            ldsm_x4(fb[buf][nj * 2][0], fb[buf][nj * 2][1],
                    fb[buf][nj * 2 + 1][0], fb[buf][nj * 2 + 1][1],
                    Bs + boff + nj * (16 * HROW_B) + kofs);
    };

    load_stage(0, 0);
    asm volatile("cp.async.commit_group;" ::: "memory");
    load_stage(1, 1);
    asm volatile("cp.async.commit_group;" ::: "memory");

    for (int kt = 0; kt < KT; kt++) {
        asm volatile("cp.async.wait_group 1;" ::: "memory");
        __syncthreads();

        if (kt + 2 < KT) load_stage(kt + 2, (kt + 2) % 3);
        asm volatile("cp.async.commit_group;" ::: "memory");

        uint32_t As = smem_base + (kt % 3) * H_STAGE;
        uint32_t Bs = As + H_TILE_B;

        load_frags(As, Bs, 0, 0);
#pragma unroll
        for (int ks = 0; ks < 4; ks++) {
            int cur = ks & 1;
            if (ks < 3) load_frags(As, Bs, ks + 1, cur ^ 1);
#pragma unroll
            for (int mi = 0; mi < 4; mi++)
#pragma unroll
                for (int ni = 0; ni < 8; ni++)
                    mma_f16(acc[mi][ni],
                            fa[cur][mi][0], fa[cur][mi][1],
                            fa[cur][mi][2], fa[cur][mi][3],
                            fb[cur][ni][0], fb[cur][ni][1]);
        }
    }

#pragma unroll
    for (int mi = 0; mi < 4; mi++) {
        int row0 = m0 + wm * 64 + mi * 16 + g;
#pragma unroll
        for (int ni = 0; ni < 8; ni++) {
            int col = n0 + wn * 64 + ni * 8 + tg * 2;
            float2 v0 = make_float2(acc[mi][ni][0], acc[mi][ni][1]);
            float2 v1 = make_float2(acc[mi][ni][2], acc[mi][ni][3]);
            if (BIAS) {
                float2 b2 = *(const float2*)(bias + col);
                v0.x += b2.x; v0.y += b2.y;
                v1.x += b2.x; v1.y += b2.y;
            }
            if (RELU && col < relu_cols) {
                v0.x = fmaxf(v0.x, 0.f); v0.y = fmaxf(v0.y, 0.f);
                v1.x = fmaxf(v1.x, 0.f); v1.y = fmaxf(v1.y, 0.f);
            }
            if constexpr (sizeof(OutT) == 2) {
                *(half2*)((__half*)C + (size_t)row0 * N + col) =
                    __floats2half2_rn(v0.x, v0.y);
                *(half2*)((__half*)C + (size_t)(row0 + 8) * N + col) =
                    __floats2half2_rn(v1.x, v1.y);
            } else {
                *(float2*)((float*)C + (size_t)row0 * N + col) = v0;
                *(float2*)((float*)C + (size_t)(row0 + 8) * N + col) = v1;
            }
        }
    }
}

// ------------------------- K4: kv + ksum via tensor cores (8 splits) ---------
constexpr int KVROW_B   = 144;
constexpr int KV_TILE_B = 64 * KVROW_B;            // 9216
constexpr int KV_STAGE  = 2 * KV_TILE_B;           // 18432
constexpr int KV_SMEM   = 3 * KV_STAGE;            // 55296

__global__ __launch_bounds__(128)
void kv_mma_kernel()
{
    extern __shared__ char skv[];
    const uint32_t sb = smem_u32(skv);
    const int tid = threadIdx.x;
    const int wid = tid >> 5;
    const int lane = tid & 31;
    const int split = blockIdx.x;
    const int bh = blockIdx.y;
    const int b = bh >> 4, h = bh & 15;
    const size_t base_row = (size_t)b * 4096 + split * 512;
    const __half* PKg = g_PHIVH + 1024 + h * 64;
    const __half* VVg = g_PHIVH + 2048 + h * 64;

    auto load_chunk = [&](int c, int buf) {
        uint32_t pb = sb + buf * KV_STAGE;
        uint32_t vb = pb + KV_TILE_B;
        size_t row0 = base_row + c * 64;
#pragma unroll
        for (int j = 0; j < 4; j++) {
            int o = tid + j * 128;
            int r = o >> 3, cc = o & 7;
            size_t off = (row0 + r) * 3072 + cc * 8;
            cp16(pb + (uint32_t)(r * KVROW_B + cc * 16), PKg + off);
            cp16(vb + (uint32_t)(r * KVROW_B + cc * 16), VVg + off);
        }
    };

    const uint32_t a_off = (uint32_t)((((lane & 16) ? 8 : 0) + (lane & 7)) * KVROW_B
                                      + wid * 32 + ((lane & 8) ? 16 : 0));
    const uint32_t b_off = (uint32_t)((((lane & 8) ? 8 : 0) + (lane & 7)) * KVROW_B
                                      + ((lane & 16) ? 16 : 0));

    float acc[8][4];
#pragma unroll
    for (int ni = 0; ni < 8; ni++)
#pragma unroll
        for (int q = 0; q < 4; q++) acc[ni][q] = 0.f;
    float ks = 0.f;

    load_chunk(0, 0);
    asm volatile("cp.async.commit_group;" ::: "memory");
    load_chunk(1, 1);
    asm volatile("cp.async.commit_group;" ::: "memory");

    for (int c = 0; c < 8; c++) {
        asm volatile("cp.async.wait_group 1;" ::: "memory");
        __syncthreads();
        if (c + 2 < 8) load_chunk(c + 2, (c + 2) % 3);
        asm volatile("cp.async.commit_group;" ::: "memory");

        uint32_t pb = sb + (c % 3) * KV_STAGE;
        uint32_t vb = pb + KV_TILE_B;

        if (tid < 64) {
            const __half* pk = (const __half*)(skv + (c % 3) * KV_STAGE);
#pragma unroll 8
            for (int n = 0; n < 64; n++)
                ks += __half2float(*(const __half*)((const char*)pk
                                                    + n * KVROW_B + tid * 2));
        }

#pragma unroll
        for (int kk = 0; kk < 4; kk++) {
            uint32_t a0, a1, a2, a3;
            ldsm_x4_t(a0, a1, a2, a3, pb + kk * (16 * KVROW_B) + a_off);
#pragma unroll
            for (int eb = 0; eb < 4; eb++) {
                uint32_t r0, r1, r2, r3;
                ldsm_x4_t(r0, r1, r2, r3,
                          vb + kk * (16 * KVROW_B) + b_off + eb * 32);
                mma_f16(acc[eb * 2],     a0, a1, a2, a3, r0, r1);
                mma_f16(acc[eb * 2 + 1], a0, a1, a2, a3, r2, r3);
            }
        }
    }

    float* dst = g_KVP + (size_t)(split * 64 + bh) * 4096;
    int g = lane >> 2, tg = lane & 3;
#pragma unroll
    for (int ni = 0; ni < 8; ni++) {
        int e = ni * 8 + tg * 2;
        int d0 = wid * 16 + g;
        dst[d0 * 64 + e]           = acc[ni][0];
        dst[d0 * 64 + e + 1]       = acc[ni][1];
        dst[(d0 + 8) * 64 + e]     = acc[ni][2];
        dst[(d0 + 8) * 64 + e + 1] = acc[ni][3];
    }
    if (tid < 64) g_KSP[(split * 64 + bh) * 64 + tid] = ks;
}

// ------------------------- K5: vectorized reduction -> fp16 kv [d][e] --------
// grid 272x256: idx<65536 handles 4 contiguous kv elems; tail does ksum.
__global__ __launch_bounds__(256)
void kv_reduce_kernel()
{
    int idx = blockIdx.x * 256 + threadIdx.x;
    if (idx < 65536) {
        int bh = idx >> 10;
        int r4 = (idx & 1023) * 4;
        float4 s = make_float4(0.f, 0.f, 0.f, 0.f);
#pragma unroll
        for (int sp = 0; sp < 8; sp++) {
            float4 v = *(const float4*)(g_KVP
                + (size_t)(sp * 64 + bh) * 4096 + r4);
            s.x += v.x; s.y += v.y; s.z += v.z; s.w += v.w;
        }
        half2 h0 = __floats2half2_rn(s.x, s.y);
        half2 h1 = __floats2half2_rn(s.z, s.w);
        uint2 u = make_uint2(*(uint32_t*)&h0, *(uint32_t*)&h1);
        *(uint2*)(g_KVH + ((size_t)bh << 12) + r4) = u;
    } else {
        int j = idx - 65536;
        if (j < 64 * 64) {
            int bh = j >> 6, d = j & 63;
            float s = 0.f;
#pragma unroll
            for (int sp = 0; sp < 8; sp++)
                s += g_KSP[(sp * 64 + bh) * 64 + d];
            g_KSUM[j] = s;
        }
    }
}

// ------------------------- K6: attn via tensor cores -------------------------
// attn[n,e] = inv[n] * sum_d phiQ[n,d] * kv[d,e]; kv fp16 [d][e] in g_KVH,
// consumed with ldmatrix.trans (same mapping as kv_mma's B operand).
__global__ __launch_bounds__(128)
void attn_mma_kernel()
{
    __shared__ __align__(16) char sPQ[128 * 144];
    __shared__ __align__(16) char sKV[64 * 144];
    __shared__ float sDen[128];
    __shared__ float sKS[64];

    const int tid = threadIdx.x;
    const int wid = tid >> 5;
    const int lane = tid & 31;
    const int chunk = blockIdx.x;
    const int bh = blockIdx.y;
    const int b = bh >> 4, h = bh & 15;
    const size_t m0 = (size_t)b * 4096 + chunk * 128;

    const uint32_t pqb = smem_u32(sPQ);
    const uint32_t kvb = smem_u32(sKV);

    const __half* PQg = g_PHIVH + h * 64;
#pragma unroll
    for (int j = 0; j < 8; j++) {
        int o = tid + j * 128;
        int r = o >> 3, cc = o & 7;
        cp16(pqb + (uint32_t)(r * 144 + cc * 16), PQg + (m0 + r) * 3072 + cc * 8);
    }
    const __half* KVg = g_KVH + ((size_t)bh << 12);
#pragma unroll
    for (int j = 0; j < 4; j++) {
        int o = tid + j * 128;
        int r = o >> 3, cc = o & 7;
        cp16(kvb + (uint32_t)(r * 144 + cc * 16), KVg + r * 64 + cc * 8);
    }
    asm volatile("cp.async.commit_group;" ::: "memory");
    if (tid < 64) sKS[tid] = g_KSUM[bh * 64 + tid];
    asm volatile("cp.async.wait_group 0;" ::: "memory");
    __syncthreads();

    {
        const __half* pq = (const __half*)(sPQ + tid * 144);
        float den = 0.f;
#pragma unroll 16
        for (int d = 0; d < 64; d++)
            den += __half2float(pq[d]) * sKS[d];
        sDen[tid] = 1.0f / (0.125f * den + 1e-8f);
    }

    const uint32_t aoff = pqb + (uint32_t)((wid * 32 + (lane & 15)) * 144
                                           + ((lane & 16) ? 16 : 0));
    // trans-B from [d][e] rows: row term (k within 16-block), col quadrants
    const uint32_t boff = kvb + (uint32_t)((((lane & 8) ? 8 : 0) + (lane & 7)) * 144
                                           + ((lane & 16) ? 16 : 0));

    float acc[2][8][4];
#pragma unroll
    for (int mi = 0; mi < 2; mi++)
#pragma unroll
        for (int ni = 0; ni < 8; ni++)
#pragma unroll
            for (int q = 0; q < 4; q++) acc[mi][ni][q] = 0.f;

#pragma unroll
    for (int ksb = 0; ksb < 4; ksb++) {
        uint32_t af[2][4];
#pragma unroll
        for (int mi = 0; mi < 2; mi++)
            ldsm_x4(af[mi][0], af[mi][1], af[mi][2], af[mi][3],
                    aoff + mi * (16 * 144) + ksb * 32);
        uint32_t bf[8][2];
#pragma unroll
        for (int nj = 0; nj < 4; nj++)
            ldsm_x4_t(bf[nj * 2][0], bf[nj * 2][1],
                      bf[nj * 2 + 1][0], bf[nj * 2 + 1][1],
                      boff + ksb * (16 * 144) + nj * 32);
#pragma unroll
        for (int mi = 0; mi < 2; mi++)
#pragma unroll
            for (int ni = 0; ni < 8; ni++)
                mma_f16(acc[mi][ni], af[mi][0], af[mi][1], af[mi][2],
                        af[mi][3], bf[ni][0], bf[ni][1]);
    }
    __syncthreads();

    const int g = lane >> 2, tg = lane & 3;
#pragma unroll
    for (int mi = 0; mi < 2; mi++) {
        int row = wid * 32 + mi * 16 + g;
        float inv0 = sDen[row], inv1 = sDen[row + 8];
        __half* dst0 = g_ATTNH + (m0 + row) * 1024 + h * 64;
#pragma unroll
        for (int ni = 0; ni < 8; ni++) {
            int e = ni * 8 + tg * 2;
            *(half2*)(dst0 + e) =
                __floats2half2_rn(acc[mi][ni][0] * inv0, acc[mi][ni][1] * inv0);
            *(half2*)(dst0 + 8 * 1024 + e) =
                __floats2half2_rn(acc[mi][ni][2] * inv1, acc[mi][ni][3] * inv1);
        }
    }
}

// ------------------------- launch -------------------------------------------
extern "C" void kernel_launch(void* const* d_in, const int* in_sizes, int n_in,
                              void* d_out, int out_size)
{
    const float* query = (const float*)d_in[0];
    const float* Wq    = (const float*)d_in[1];
    const float* Wk    = (const float*)d_in[2];
    const float* Wv    = (const float*)d_in[3];
    const float* P     = (const float*)d_in[4];
    const float* Wo    = (const float*)d_in[5];
    const float* bo    = (const float*)d_in[6];
    float* out = (float*)d_out;

    void *p_xh, *p_wbigh, *p_worh, *p_attnh, *p_phivh;
    cudaGetSymbolAddress(&p_xh,     g_XH);
    cudaGetSymbolAddress(&p_wbigh,  g_WBIGH);
    cudaGetSymbolAddress(&p_worh,   g_WORH);
    cudaGetSymbolAddress(&p_attnh,  g_ATTNH);
    cudaGetSymbolAddress(&p_phivh,  g_PHIVH);

    cudaFuncSetAttribute((const void*)gemm_mma<__half, true, false>,
                         cudaFuncAttributeMaxDynamicSharedMemorySize, GEMM_SMEM);
    cudaFuncSetAttribute((const void*)gemm_mma<float, false, true>,
                         cudaFuncAttributeMaxDynamicSharedMemorySize, GEMM_SMEM);
    cudaFuncSetAttribute((const void*)kv_mma_kernel,
                         cudaFuncAttributeMaxDynamicSharedMemorySize, KV_SMEM);

    // fused prologue: weff + Wv copy + Wo round + query round, one launch
    prologue_kernel<<<10240, 256>>>(Wq, Wk, P, Wv, query, Wo);

    // PHIVH = relu(XH @ WBIGH^T) on first 2048 cols (fp16 out)
    gemm_mma<__half, true, false><<<dim3(24, 128), 128, GEMM_SMEM>>>(
        (const __half*)p_xh, (const __half*)p_wbigh, nullptr,
        (__half*)p_phivh, 16384, 3072, 1024, 2048);

    kv_mma_kernel<<<dim3(8, 64), 128, KV_SMEM>>>();
    kv_reduce_kernel<<<272, 256>>>();
    attn_mma_kernel<<<dim3(32, 64), 128>>>();   // writes fp16 ATTN

    // out = ATTNH @ WORH^T + bo (fp32 out)
    gemm_mma<float, false, true><<<dim3(8, 128), 128, GEMM_SMEM>>>(
        (const __half*)p_attnh, (const __half*)p_worh, bo, out,
        16384, 1024, 1024, 0);
}

// round 15
// speedup vs baseline: 1.0917x; 1.0450x over previous
#include <cuda_runtime.h>
#include <cuda_fp16.h>
#include <cstdint>

// ---------------------------------------------------------------------------
// FastAttention — linear attention with ReLU feature maps.
// Big GEMMs: fp16 mma m16n8k16, CTA 128x128x64, 128 thr (warp 64x64),
// 2-stage cp.async (144B rows), 3 CTAs/SM (12 warps). kv/attn on tensor
// cores. Vectorized prologue + reduce (R14).
// ---------------------------------------------------------------------------

// ------------------------- device scratch (no allocs) ----------------------
__device__ __align__(16) __half g_XH[(size_t)16384 * 1024];
__device__ __align__(16) __half g_WBIGH[(size_t)3072 * 1024];
__device__ __align__(16) __half g_WORH[(size_t)1024 * 1024];
__device__ __align__(16) __half g_ATTNH[(size_t)16384 * 1024];
__device__ __align__(16) __half g_PHIVH[(size_t)16384 * 3072];
__device__ __align__(16) __half g_KVH[64 * 64 * 64];    // [bh][d][e] fp16
__device__ float g_KSUM[64 * 64];
__device__ float g_KVP[8 * 64 * 64 * 64];
__device__ float g_KSP[8 * 64 * 64];

// ------------------------- helpers ------------------------------------------
__device__ __forceinline__ uint32_t smem_u32(const void* p) {
    uint32_t a;
    asm("{ .reg .u64 t; cvta.to.shared.u64 t, %1; cvt.u32.u64 %0, t; }"
        : "=r"(a) : "l"(p));
    return a;
}
__device__ __forceinline__ void cp16(uint32_t dst, const void* src) {
    asm volatile("cp.async.cg.shared.global [%0], [%1], 16;" :: "r"(dst), "l"(src));
}
__device__ __forceinline__ void ldsm_x4(uint32_t& r0, uint32_t& r1,
                                        uint32_t& r2, uint32_t& r3, uint32_t a) {
    asm volatile("ldmatrix.sync.aligned.m8n8.x4.shared.b16 {%0,%1,%2,%3}, [%4];"
                 : "=r"(r0), "=r"(r1), "=r"(r2), "=r"(r3) : "r"(a));
}
__device__ __forceinline__ void ldsm_x4_t(uint32_t& r0, uint32_t& r1,
                                          uint32_t& r2, uint32_t& r3, uint32_t a) {
    asm volatile("ldmatrix.sync.aligned.m8n8.x4.trans.shared.b16 {%0,%1,%2,%3}, [%4];"
                 : "=r"(r0), "=r"(r1), "=r"(r2), "=r"(r3) : "r"(a));
}
__device__ __forceinline__ void mma_f16(float* c, uint32_t a0, uint32_t a1,
                                        uint32_t a2, uint32_t a3,
                                        uint32_t b0, uint32_t b1) {
    asm volatile(
        "mma.sync.aligned.m16n8k16.row.col.f32.f16.f16.f32 "
        "{%0,%1,%2,%3}, {%4,%5,%6,%7}, {%8,%9}, {%0,%1,%2,%3};"
        : "+f"(c[0]), "+f"(c[1]), "+f"(c[2]), "+f"(c[3])
        : "r"(a0), "r"(a1), "r"(a2), "r"(a3), "r"(b0), "r"(b1));
}

// ------------------------- fused prologue ------------------------------------
// blocks [0,512):      Weff fold (Wq/Wk x per-head P) -> WBIGH fp16
// blocks [512,1536):   Wv rows -> WBIGH fp16
// blocks [1536,2048):  Wo -> WORH fp16      (8 floats/thread, 16B stores)
// blocks [2048,10240): query -> XH fp16     (8 floats/thread, 16B stores)
__global__ __launch_bounds__(256)
void prologue_kernel(const float* __restrict__ Wq,
                     const float* __restrict__ Wk,
                     const float* __restrict__ P,
                     const float* __restrict__ Wv,
                     const float* __restrict__ query,
                     const float* __restrict__ Wo)
{
    int bid = blockIdx.x;
    int tid = threadIdx.x;

    if (bid < 512) {
        int which = bid >> 8;
        int rem   = bid & 255;
        int h     = rem >> 4;
        int chunk = rem & 15;
        const float* W = which ? Wk : Wq;

        __shared__ float Psh[64][64];
        __shared__ float Wsh[64][64];
#pragma unroll
        for (int i = 0; i < 4; i++) {
            int f = tid + i * 256;
            int e = f >> 4, c4 = (f & 15) << 2;
            *(float4*)&Psh[e][c4] = *(const float4*)(P + (size_t)h * 4096 + f * 4);
            *(float4*)&Wsh[e][c4] =
                *(const float4*)(W + (size_t)(h * 64 + e) * 1024 + chunk * 64 + c4);
        }
        __syncthreads();

        int dp = tid & 63;
        int dg = tid >> 6;
        float acc[16];
#pragma unroll
        for (int j = 0; j < 16; j++) acc[j] = 0.f;
#pragma unroll 4
        for (int e = 0; e < 64; e++) {
            float p = Psh[e][dp];
#pragma unroll
            for (int j = 0; j < 16; j++)
                acc[j] += p * Wsh[e][dg * 16 + j];
        }
        __half* dst = g_WBIGH + (size_t)(which * 1024 + h * 64 + dp) * 1024
                              + chunk * 64 + dg * 16;
#pragma unroll
        for (int j = 0; j < 16; j += 8) {
            half2 h0 = __floats2half2_rn(acc[j],     acc[j + 1]);
            half2 h1 = __floats2half2_rn(acc[j + 2], acc[j + 3]);
            half2 h2 = __floats2half2_rn(acc[j + 4], acc[j + 5]);
            half2 h3 = __floats2half2_rn(acc[j + 6], acc[j + 7]);
            uint4 u = make_uint4(*(uint32_t*)&h0, *(uint32_t*)&h1,
                                 *(uint32_t*)&h2, *(uint32_t*)&h3);
            *(uint4*)(dst + j) = u;
        }
    } else if (bid < 1536) {
        int row = bid - 512;
        float4 v = *(const float4*)(Wv + (size_t)row * 1024 + tid * 4);
        __half* dst = g_WBIGH + (size_t)(2048 + row) * 1024 + tid * 4;
        half2 h0 = __floats2half2_rn(v.x, v.y);
        half2 h1 = __floats2half2_rn(v.z, v.w);
        uint2 u = make_uint2(*(uint32_t*)&h0, *(uint32_t*)&h1);
        *(uint2*)(dst) = u;
    } else if (bid < 2048) {
        size_t i = ((size_t)(bid - 1536) * 256 + tid) * 8;
        float4 v0 = *(const float4*)(Wo + i);
        float4 v1 = *(const float4*)(Wo + i + 4);
        half2 h0 = __floats2half2_rn(v0.x, v0.y);
        half2 h1 = __floats2half2_rn(v0.z, v0.w);
        half2 h2 = __floats2half2_rn(v1.x, v1.y);
        half2 h3 = __floats2half2_rn(v1.z, v1.w);
        uint4 u = make_uint4(*(uint32_t*)&h0, *(uint32_t*)&h1,
                             *(uint32_t*)&h2, *(uint32_t*)&h3);
        *(uint4*)(g_WORH + i) = u;
    } else {
        size_t i = ((size_t)(bid - 2048) * 256 + tid) * 8;
        float4 v0 = *(const float4*)(query + i);
        float4 v1 = *(const float4*)(query + i + 4);
        half2 h0 = __floats2half2_rn(v0.x, v0.y);
        half2 h1 = __floats2half2_rn(v0.z, v0.w);
        half2 h2 = __floats2half2_rn(v1.x, v1.y);
        half2 h3 = __floats2half2_rn(v1.z, v1.w);
        uint4 u = make_uint4(*(uint32_t*)&h0, *(uint32_t*)&h1,
                             *(uint32_t*)&h2, *(uint32_t*)&h3);
        *(uint4*)(g_XH + i) = u;
    }
}

// ------------------------- fp16 mma GEMM (k64, 2-stage, occ 3) --------------
constexpr int HROW_B   = 144;                      // 128B data + 16B pad
constexpr int H_TILE_B = 128 * HROW_B;             // 18432 per A/B tile
constexpr int H_STAGE  = 2 * H_TILE_B;             // 36864
constexpr int H_STAGES = 2;
constexpr int GEMM_SMEM = H_STAGES * H_STAGE;      // 73728 B

template<typename OutT, bool RELU, bool BIAS>
__global__ __launch_bounds__(128, 3)
void gemm_mma(const __half* __restrict__ A, const __half* __restrict__ Bm,
              const float* __restrict__ bias, OutT* __restrict__ C,
              int M, int N, int K, int relu_cols)
{
    extern __shared__ char smem[];
    const int tid = threadIdx.x;
    const int m0 = blockIdx.y * 128;
    const int n0 = blockIdx.x * 128;
    const int KT = K >> 6;                         // chunks of 64 halfs

    const uint32_t smem_base = smem_u32(smem);

    auto load_stage = [&](int kt, int buf) {
        uint32_t ab = smem_base + buf * H_STAGE;
        uint32_t bb = ab + H_TILE_B;
        const __half* Asrc = A + (size_t)m0 * K + kt * 64;
        const __half* Bsrc = Bm + (size_t)n0 * K + kt * 64;
#pragma unroll
        for (int j = 0; j < 8; j++) {              // 1024 cp16 per tile
            int o = tid + j * 128;
            int r = o >> 3, cc = o & 7;
            cp16(ab + (uint32_t)(r * HROW_B + cc * 16),
                 Asrc + (size_t)r * K + cc * 8);
            cp16(bb + (uint32_t)(r * HROW_B + cc * 16),
                 Bsrc + (size_t)r * K + cc * 8);
        }
    };

    const int wid  = tid >> 5;
    const int lane = tid & 31;
    const int wm = wid & 1;
    const int wn = wid >> 1;
    const int g  = lane >> 2;
    const int tg = lane & 3;

    const uint32_t aoff = (uint32_t)((wm * 64 + (lane & 15)) * HROW_B
                                     + ((lane & 16) ? 16 : 0));
    const uint32_t boff = (uint32_t)((wn * 64 + ((lane & 16) ? 8 : 0)
                                      + (lane & 7)) * HROW_B
                                     + ((lane & 8) ? 16 : 0));

    float acc[4][8][4];
#pragma unroll
    for (int mi = 0; mi < 4; mi++)
#pragma unroll
        for (int ni = 0; ni < 8; ni++)
#pragma unroll
            for (int q = 0; q < 4; q++) acc[mi][ni][q] = 0.f;

    load_stage(0, 0);
    asm volatile("cp.async.commit_group;" ::: "memory");
    load_stage(1, 1);
    asm volatile("cp.async.commit_group;" ::: "memory");

    for (int kt = 0; kt < KT; kt++) {
        asm volatile("cp.async.wait_group 1;" ::: "memory");
        __syncthreads();                           // stage kt visible

        uint32_t As = smem_base + (kt & 1) * H_STAGE;
        uint32_t Bs = As + H_TILE_B;

#pragma unroll
        for (int ks = 0; ks < 4; ks++) {
            uint32_t kofs = (uint32_t)ks * 32;
            uint32_t fa[4][4], fb[8][2];
#pragma unroll
            for (int mi = 0; mi < 4; mi++)
                ldsm_x4(fa[mi][0], fa[mi][1], fa[mi][2], fa[mi][3],
                        As + aoff + mi * (16 * HROW_B) + kofs);
#pragma unroll
            for (int nj = 0; nj < 4; nj++)
                ldsm_x4(fb[nj * 2][0], fb[nj * 2][1],
                        fb[nj * 2 + 1][0], fb[nj * 2 + 1][1],
                        Bs + boff + nj * (16 * HROW_B) + kofs);
#pragma unroll
            for (int mi = 0; mi < 4; mi++)
#pragma unroll
                for (int ni = 0; ni < 8; ni++)
                    mma_f16(acc[mi][ni], fa[mi][0], fa[mi][1], fa[mi][2],
                            fa[mi][3], fb[ni][0], fb[ni][1]);
        }

        __syncthreads();                           // all warps done with buf
        if (kt + 2 < KT) load_stage(kt + 2, kt & 1);
        asm volatile("cp.async.commit_group;" ::: "memory");
    }

#pragma unroll
    for (int mi = 0; mi < 4; mi++) {
        int row0 = m0 + wm * 64 + mi * 16 + g;
#pragma unroll
        for (int ni = 0; ni < 8; ni++) {
            int col = n0 + wn * 64 + ni * 8 + tg * 2;
            float2 v0 = make_float2(acc[mi][ni][0], acc[mi][ni][1]);
            float2 v1 = make_float2(acc[mi][ni][2], acc[mi][ni][3]);
            if (BIAS) {
                float2 b2 = *(const float2*)(bias + col);
                v0.x += b2.x; v0.y += b2.y;
                v1.x += b2.x; v1.y += b2.y;
            }
            if (RELU && col < relu_cols) {
                v0.x = fmaxf(v0.x, 0.f); v0.y = fmaxf(v0.y, 0.f);
                v1.x = fmaxf(v1.x, 0.f); v1.y = fmaxf(v1.y, 0.f);
            }
            if constexpr (sizeof(OutT) == 2) {
                *(half2*)((__half*)C + (size_t)row0 * N + col) =
                    __floats2half2_rn(v0.x, v0.y);
                *(half2*)((__half*)C + (size_t)(row0 + 8) * N + col) =
                    __floats2half2_rn(v1.x, v1.y);
            } else {
                *(float2*)((float*)C + (size_t)row0 * N + col) = v0;
                *(float2*)((float*)C + (size_t)(row0 + 8) * N + col) = v1;
            }
        }
    }
}

// ------------------------- K4: kv + ksum via tensor cores (8 splits) ---------
constexpr int KVROW_B   = 144;
constexpr int KV_TILE_B = 64 * KVROW_B;            // 9216
constexpr int KV_STAGE  = 2 * KV_TILE_B;           // 18432
constexpr int KV_SMEM   = 3 * KV_STAGE;            // 55296

__global__ __launch_bounds__(128)
void kv_mma_kernel()
{
    extern __shared__ char skv[];
    const uint32_t sb = smem_u32(skv);
    const int tid = threadIdx.x;
    const int wid = tid >> 5;
    const int lane = tid & 31;
    const int split = blockIdx.x;
    const int bh = blockIdx.y;
    const int b = bh >> 4, h = bh & 15;
    const size_t base_row = (size_t)b * 4096 + split * 512;
    const __half* PKg = g_PHIVH + 1024 + h * 64;
    const __half* VVg = g_PHIVH + 2048 + h * 64;

    auto load_chunk = [&](int c, int buf) {
        uint32_t pb = sb + buf * KV_STAGE;
        uint32_t vb = pb + KV_TILE_B;
        size_t row0 = base_row + c * 64;
#pragma unroll
        for (int j = 0; j < 4; j++) {
            int o = tid + j * 128;
            int r = o >> 3, cc = o & 7;
            size_t off = (row0 + r) * 3072 + cc * 8;
            cp16(pb + (uint32_t)(r * KVROW_B + cc * 16), PKg + off);
            cp16(vb + (uint32_t)(r * KVROW_B + cc * 16), VVg + off);
        }
    };

    const uint32_t a_off = (uint32_t)((((lane & 16) ? 8 : 0) + (lane & 7)) * KVROW_B
                                      + wid * 32 + ((lane & 8) ? 16 : 0));
    const uint32_t b_off = (uint32_t)((((lane & 8) ? 8 : 0) + (lane & 7)) * KVROW_B
                                      + ((lane & 16) ? 16 : 0));

    float acc[8][4];
#pragma unroll
    for (int ni = 0; ni < 8; ni++)
#pragma unroll
        for (int q = 0; q < 4; q++) acc[ni][q] = 0.f;
    float ks = 0.f;

    load_chunk(0, 0);
    asm volatile("cp.async.commit_group;" ::: "memory");
    load_chunk(1, 1);
    asm volatile("cp.async.commit_group;" ::: "memory");

    for (int c = 0; c < 8; c++) {
        asm volatile("cp.async.wait_group 1;" ::: "memory");
        __syncthreads();
        if (c + 2 < 8) load_chunk(c + 2, (c + 2) % 3);
        asm volatile("cp.async.commit_group;" ::: "memory");

        uint32_t pb = sb + (c % 3) * KV_STAGE;
        uint32_t vb = pb + KV_TILE_B;

        if (tid < 64) {
            const __half* pk = (const __half*)(skv + (c % 3) * KV_STAGE);
#pragma unroll 8
            for (int n = 0; n < 64; n++)
                ks += __half2float(*(const __half*)((const char*)pk
                                                    + n * KVROW_B + tid * 2));
        }

#pragma unroll
        for (int kk = 0; kk < 4; kk++) {
            uint32_t a0, a1, a2, a3;
            ldsm_x4_t(a0, a1, a2, a3, pb + kk * (16 * KVROW_B) + a_off);
#pragma unroll
            for (int eb = 0; eb < 4; eb++) {
                uint32_t r0, r1, r2, r3;
                ldsm_x4_t(r0, r1, r2, r3,
                          vb + kk * (16 * KVROW_B) + b_off + eb * 32);
                mma_f16(acc[eb * 2],     a0, a1, a2, a3, r0, r1);
                mma_f16(acc[eb * 2 + 1], a0, a1, a2, a3, r2, r3);
            }
        }
    }

    float* dst = g_KVP + (size_t)(split * 64 + bh) * 4096;
    int g = lane >> 2, tg = lane & 3;
#pragma unroll
    for (int ni = 0; ni < 8; ni++) {
        int e = ni * 8 + tg * 2;
        int d0 = wid * 16 + g;
        dst[d0 * 64 + e]           = acc[ni][0];
        dst[d0 * 64 + e + 1]       = acc[ni][1];
        dst[(d0 + 8) * 64 + e]     = acc[ni][2];
        dst[(d0 + 8) * 64 + e + 1] = acc[ni][3];
    }
    if (tid < 64) g_KSP[(split * 64 + bh) * 64 + tid] = ks;
}

// ------------------------- K5: vectorized reduction -> fp16 kv [d][e] --------
__global__ __launch_bounds__(256)
void kv_reduce_kernel()
{
    int idx = blockIdx.x * 256 + threadIdx.x;
    if (idx < 65536) {
        int bh = idx >> 10;
        int r4 = (idx & 1023) * 4;
        float4 s = make_float4(0.f, 0.f, 0.f, 0.f);
#pragma unroll
        for (int sp = 0; sp < 8; sp++) {
            float4 v = *(const float4*)(g_KVP
                + (size_t)(sp * 64 + bh) * 4096 + r4);
            s.x += v.x; s.y += v.y; s.z += v.z; s.w += v.w;
        }
        half2 h0 = __floats2half2_rn(s.x, s.y);
        half2 h1 = __floats2half2_rn(s.z, s.w);
        uint2 u = make_uint2(*(uint32_t*)&h0, *(uint32_t*)&h1);
        *(uint2*)(g_KVH + ((size_t)bh << 12) + r4) = u;
    } else {
        int j = idx - 65536;
        if (j < 64 * 64) {
            int bh = j >> 6, d = j & 63;
            float s = 0.f;
#pragma unroll
            for (int sp = 0; sp < 8; sp++)
                s += g_KSP[(sp * 64 + bh) * 64 + d];
            g_KSUM[j] = s;
        }
    }
}

// ------------------------- K6: attn via tensor cores -------------------------
__global__ __launch_bounds__(128)
void attn_mma_kernel()
{
    __shared__ __align__(16) char sPQ[128 * 144];
    __shared__ __align__(16) char sKV[64 * 144];
    __shared__ float sDen[128];
    __shared__ float sKS[64];

    const int tid = threadIdx.x;
    const int wid = tid >> 5;
    const int lane = tid & 31;
    const int chunk = blockIdx.x;
    const int bh = blockIdx.y;
    const int b = bh >> 4, h = bh & 15;
    const size_t m0 = (size_t)b * 4096 + chunk * 128;

    const uint32_t pqb = smem_u32(sPQ);
    const uint32_t kvb = smem_u32(sKV);

    const __half* PQg = g_PHIVH + h * 64;
#pragma unroll
    for (int j = 0; j < 8; j++) {
        int o = tid + j * 128;
        int r = o >> 3, cc = o & 7;
        cp16(pqb + (uint32_t)(r * 144 + cc * 16), PQg + (m0 + r) * 3072 + cc * 8);
    }
    const __half* KVg = g_KVH + ((size_t)bh << 12);
#pragma unroll
    for (int j = 0; j < 4; j++) {
        int o = tid + j * 128;
        int r = o >> 3, cc = o & 7;
        cp16(kvb + (uint32_t)(r * 144 + cc * 16), KVg + r * 64 + cc * 8);
    }
    asm volatile("cp.async.commit_group;" ::: "memory");
    if (tid < 64) sKS[tid] = g_KSUM[bh * 64 + tid];
    asm volatile("cp.async.wait_group 0;" ::: "memory");
    __syncthreads();

    {
        const __half* pq = (const __half*)(sPQ + tid * 144);
        float den = 0.f;
#pragma unroll 16
        for (int d = 0; d < 64; d++)
            den += __half2float(pq[d]) * sKS[d];
        sDen[tid] = 1.0f / (0.125f * den + 1e-8f);
    }

    const uint32_t aoff = pqb + (uint32_t)((wid * 32 + (lane & 15)) * 144
                                           + ((lane & 16) ? 16 : 0));
    const uint32_t boff = kvb + (uint32_t)((((lane & 8) ? 8 : 0) + (lane & 7)) * 144
                                           + ((lane & 16) ? 16 : 0));

    float acc[2][8][4];
#pragma unroll
    for (int mi = 0; mi < 2; mi++)
#pragma unroll
        for (int ni = 0; ni < 8; ni++)
#pragma unroll
            for (int q = 0; q < 4; q++) acc[mi][ni][q] = 0.f;

#pragma unroll
    for (int ksb = 0; ksb < 4; ksb++) {
        uint32_t af[2][4];
#pragma unroll
        for (int mi = 0; mi < 2; mi++)
            ldsm_x4(af[mi][0], af[mi][1], af[mi][2], af[mi][3],
                    aoff + mi * (16 * 144) + ksb * 32);
        uint32_t bf[8][2];
#pragma unroll
        for (int nj = 0; nj < 4; nj++)
            ldsm_x4_t(bf[nj * 2][0], bf[nj * 2][1],
                      bf[nj * 2 + 1][0], bf[nj * 2 + 1][1],
                      boff + ksb * (16 * 144) + nj * 32);
#pragma unroll
        for (int mi = 0; mi < 2; mi++)
#pragma unroll
            for (int ni = 0; ni < 8; ni++)
                mma_f16(acc[mi][ni], af[mi][0], af[mi][1], af[mi][2],
                        af[mi][3], bf[ni][0], bf[ni][1]);
    }
    __syncthreads();

    const int g = lane >> 2, tg = lane & 3;
#pragma unroll
    for (int mi = 0; mi < 2; mi++) {
        int row = wid * 32 + mi * 16 + g;
        float inv0 = sDen[row], inv1 = sDen[row + 8];
        __half* dst0 = g_ATTNH + (m0 + row) * 1024 + h * 64;
#pragma unroll
        for (int ni = 0; ni < 8; ni++) {
            int e = ni * 8 + tg * 2;
            *(half2*)(dst0 + e) =
                __floats2half2_rn(acc[mi][ni][0] * inv0, acc[mi][ni][1] * inv0);
            *(half2*)(dst0 + 8 * 1024 + e) =
                __floats2half2_rn(acc[mi][ni][2] * inv1, acc[mi][ni][3] * inv1);
        }
    }
}

// ------------------------- launch -------------------------------------------
extern "C" void kernel_launch(void* const* d_in, const int* in_sizes, int n_in,
                              void* d_out, int out_size)
{
    const float* query = (const float*)d_in[0];
    const float* Wq    = (const float*)d_in[1];
    const float* Wk    = (const float*)d_in[2];
    const float* Wv    = (const float*)d_in[3];
    const float* P     = (const float*)d_in[4];
    const float* Wo    = (const float*)d_in[5];
    const float* bo    = (const float*)d_in[6];
    float* out = (float*)d_out;

    void *p_xh, *p_wbigh, *p_worh, *p_attnh, *p_phivh;
    cudaGetSymbolAddress(&p_xh,     g_XH);
    cudaGetSymbolAddress(&p_wbigh,  g_WBIGH);
    cudaGetSymbolAddress(&p_worh,   g_WORH);
    cudaGetSymbolAddress(&p_attnh,  g_ATTNH);
    cudaGetSymbolAddress(&p_phivh,  g_PHIVH);

    cudaFuncSetAttribute((const void*)gemm_mma<__half, true, false>,
                         cudaFuncAttributeMaxDynamicSharedMemorySize, GEMM_SMEM);
    cudaFuncSetAttribute((const void*)gemm_mma<float, false, true>,
                         cudaFuncAttributeMaxDynamicSharedMemorySize, GEMM_SMEM);
    cudaFuncSetAttribute((const void*)kv_mma_kernel,
                         cudaFuncAttributeMaxDynamicSharedMemorySize, KV_SMEM);

    // fused prologue: weff + Wv copy + Wo round + query round, one launch
    prologue_kernel<<<10240, 256>>>(Wq, Wk, P, Wv, query, Wo);

    // PHIVH = relu(XH @ WBIGH^T) on first 2048 cols (fp16 out)
    gemm_mma<__half, true, false><<<dim3(24, 128), 128, GEMM_SMEM>>>(
        (const __half*)p_xh, (const __half*)p_wbigh, nullptr,
        (__half*)p_phivh, 16384, 3072, 1024, 2048);

    kv_mma_kernel<<<dim3(8, 64), 128, KV_SMEM>>>();
    kv_reduce_kernel<<<272, 256>>>();
    attn_mma_kernel<<<dim3(32, 64), 128>>>();   // writes fp16 ATTN

    // out = ATTNH @ WORH^T + bo (fp32 out)
    gemm_mma<float, false, true><<<dim3(8, 128), 128, GEMM_SMEM>>>(
        (const __half*)p_attnh, (const __half*)p_worh, bo, out,
        16384, 1024, 1024, 0);
}

// round 16
// speedup vs baseline: 1.0962x; 1.0041x over previous
#include <cuda_runtime.h>
#include <cuda_fp16.h>
#include <cstdint>

// ---------------------------------------------------------------------------
// FastAttention — linear attention with ReLU feature maps.
// Big GEMMs: fp16 mma m16n8k16, CTA 128x128x64, 128 thr (warp 64x64),
// 2-stage cp.async (144B rows), 3 CTAs/SM. kv/attn on tensor cores.
// This round: kv's ksum computed by an extra ones-column MMA (pad bytes of
// the VV tile) instead of a serial SIMT reduction loop.
// ---------------------------------------------------------------------------

// ------------------------- device scratch (no allocs) ----------------------
__device__ __align__(16) __half g_XH[(size_t)16384 * 1024];
__device__ __align__(16) __half g_WBIGH[(size_t)3072 * 1024];
__device__ __align__(16) __half g_WORH[(size_t)1024 * 1024];
__device__ __align__(16) __half g_ATTNH[(size_t)16384 * 1024];
__device__ __align__(16) __half g_PHIVH[(size_t)16384 * 3072];
__device__ __align__(16) __half g_KVH[64 * 64 * 64];    // [bh][d][e] fp16
__device__ float g_KSUM[64 * 64];
__device__ float g_KVP[8 * 64 * 64 * 64];
__device__ float g_KSP[8 * 64 * 64];

// ------------------------- helpers ------------------------------------------
__device__ __forceinline__ uint32_t smem_u32(const void* p) {
    uint32_t a;
    asm("{ .reg .u64 t; cvta.to.shared.u64 t, %1; cvt.u32.u64 %0, t; }"
        : "=r"(a) : "l"(p));
    return a;
}
__device__ __forceinline__ void cp16(uint32_t dst, const void* src) {
    asm volatile("cp.async.cg.shared.global [%0], [%1], 16;" :: "r"(dst), "l"(src));
}
__device__ __forceinline__ void ldsm_x4(uint32_t& r0, uint32_t& r1,
                                        uint32_t& r2, uint32_t& r3, uint32_t a) {
    asm volatile("ldmatrix.sync.aligned.m8n8.x4.shared.b16 {%0,%1,%2,%3}, [%4];"
                 : "=r"(r0), "=r"(r1), "=r"(r2), "=r"(r3) : "r"(a));
}
__device__ __forceinline__ void ldsm_x4_t(uint32_t& r0, uint32_t& r1,
                                          uint32_t& r2, uint32_t& r3, uint32_t a) {
    asm volatile("ldmatrix.sync.aligned.m8n8.x4.trans.shared.b16 {%0,%1,%2,%3}, [%4];"
                 : "=r"(r0), "=r"(r1), "=r"(r2), "=r"(r3) : "r"(a));
}
__device__ __forceinline__ void ldsm_x2_t(uint32_t& r0, uint32_t& r1, uint32_t a) {
    asm volatile("ldmatrix.sync.aligned.m8n8.x2.trans.shared.b16 {%0,%1}, [%2];"
                 : "=r"(r0), "=r"(r1) : "r"(a));
}
__device__ __forceinline__ void mma_f16(float* c, uint32_t a0, uint32_t a1,
                                        uint32_t a2, uint32_t a3,
                                        uint32_t b0, uint32_t b1) {
    asm volatile(
        "mma.sync.aligned.m16n8k16.row.col.f32.f16.f16.f32 "
        "{%0,%1,%2,%3}, {%4,%5,%6,%7}, {%8,%9}, {%0,%1,%2,%3};"
        : "+f"(c[0]), "+f"(c[1]), "+f"(c[2]), "+f"(c[3])
        : "r"(a0), "r"(a1), "r"(a2), "r"(a3), "r"(b0), "r"(b1));
}

// ------------------------- fused prologue ------------------------------------
__global__ __launch_bounds__(256)
void prologue_kernel(const float* __restrict__ Wq,
                     const float* __restrict__ Wk,
                     const float* __restrict__ P,
                     const float* __restrict__ Wv,
                     const float* __restrict__ query,
                     const float* __restrict__ Wo)
{
    int bid = blockIdx.x;
    int tid = threadIdx.x;

    if (bid < 512) {
        int which = bid >> 8;
        int rem   = bid & 255;
        int h     = rem >> 4;
        int chunk = rem & 15;
        const float* W = which ? Wk : Wq;

        __shared__ float Psh[64][64];
        __shared__ float Wsh[64][64];
#pragma unroll
        for (int i = 0; i < 4; i++) {
            int f = tid + i * 256;
            int e = f >> 4, c4 = (f & 15) << 2;
            *(float4*)&Psh[e][c4] = *(const float4*)(P + (size_t)h * 4096 + f * 4);
            *(float4*)&Wsh[e][c4] =
                *(const float4*)(W + (size_t)(h * 64 + e) * 1024 + chunk * 64 + c4);
        }
        __syncthreads();

        int dp = tid & 63;
        int dg = tid >> 6;
        float acc[16];
#pragma unroll
        for (int j = 0; j < 16; j++) acc[j] = 0.f;
#pragma unroll 4
        for (int e = 0; e < 64; e++) {
            float p = Psh[e][dp];
#pragma unroll
            for (int j = 0; j < 16; j++)
                acc[j] += p * Wsh[e][dg * 16 + j];
        }
        __half* dst = g_WBIGH + (size_t)(which * 1024 + h * 64 + dp) * 1024
                              + chunk * 64 + dg * 16;
#pragma unroll
        for (int j = 0; j < 16; j += 8) {
            half2 h0 = __floats2half2_rn(acc[j],     acc[j + 1]);
            half2 h1 = __floats2half2_rn(acc[j + 2], acc[j + 3]);
            half2 h2 = __floats2half2_rn(acc[j + 4], acc[j + 5]);
            half2 h3 = __floats2half2_rn(acc[j + 6], acc[j + 7]);
            uint4 u = make_uint4(*(uint32_t*)&h0, *(uint32_t*)&h1,
                                 *(uint32_t*)&h2, *(uint32_t*)&h3);
            *(uint4*)(dst + j) = u;
        }
    } else if (bid < 1536) {
        int row = bid - 512;
        float4 v = *(const float4*)(Wv + (size_t)row * 1024 + tid * 4);
        __half* dst = g_WBIGH + (size_t)(2048 + row) * 1024 + tid * 4;
        half2 h0 = __floats2half2_rn(v.x, v.y);
        half2 h1 = __floats2half2_rn(v.z, v.w);
        uint2 u = make_uint2(*(uint32_t*)&h0, *(uint32_t*)&h1);
        *(uint2*)(dst) = u;
    } else if (bid < 2048) {
        size_t i = ((size_t)(bid - 1536) * 256 + tid) * 8;
        float4 v0 = *(const float4*)(Wo + i);
        float4 v1 = *(const float4*)(Wo + i + 4);
        half2 h0 = __floats2half2_rn(v0.x, v0.y);
        half2 h1 = __floats2half2_rn(v0.z, v0.w);
        half2 h2 = __floats2half2_rn(v1.x, v1.y);
        half2 h3 = __floats2half2_rn(v1.z, v1.w);
        uint4 u = make_uint4(*(uint32_t*)&h0, *(uint32_t*)&h1,
                             *(uint32_t*)&h2, *(uint32_t*)&h3);
        *(uint4*)(g_WORH + i) = u;
    } else {
        size_t i = ((size_t)(bid - 2048) * 256 + tid) * 8;
        float4 v0 = *(const float4*)(query + i);
        float4 v1 = *(const float4*)(query + i + 4);
        half2 h0 = __floats2half2_rn(v0.x, v0.y);
        half2 h1 = __floats2half2_rn(v0.z, v0.w);
        half2 h2 = __floats2half2_rn(v1.x, v1.y);
        half2 h3 = __floats2half2_rn(v1.z, v1.w);
        uint4 u = make_uint4(*(uint32_t*)&h0, *(uint32_t*)&h1,
                             *(uint32_t*)&h2, *(uint32_t*)&h3);
        *(uint4*)(g_XH + i) = u;
    }
}

// ------------------------- fp16 mma GEMM (k64, 2-stage, occ 3) --------------
constexpr int HROW_B   = 144;                      // 128B data + 16B pad
constexpr int H_TILE_B = 128 * HROW_B;             // 18432 per A/B tile
constexpr int H_STAGE  = 2 * H_TILE_B;             // 36864
constexpr int H_STAGES = 2;
constexpr int GEMM_SMEM = H_STAGES * H_STAGE;      // 73728 B

template<typename OutT, bool RELU, bool BIAS>
__global__ __launch_bounds__(128, 3)
void gemm_mma(const __half* __restrict__ A, const __half* __restrict__ Bm,
              const float* __restrict__ bias, OutT* __restrict__ C,
              int M, int N, int K, int relu_cols)
{
    extern __shared__ char smem[];
    const int tid = threadIdx.x;
    const int m0 = blockIdx.y * 128;
    const int n0 = blockIdx.x * 128;
    const int KT = K >> 6;                         // chunks of 64 halfs

    const uint32_t smem_base = smem_u32(smem);

    auto load_stage = [&](int kt, int buf) {
        uint32_t ab = smem_base + buf * H_STAGE;
        uint32_t bb = ab + H_TILE_B;
        const __half* Asrc = A + (size_t)m0 * K + kt * 64;
        const __half* Bsrc = Bm + (size_t)n0 * K + kt * 64;
#pragma unroll
        for (int j = 0; j < 8; j++) {              // 1024 cp16 per tile
            int o = tid + j * 128;
            int r = o >> 3, cc = o & 7;
            cp16(ab + (uint32_t)(r * HROW_B + cc * 16),
                 Asrc + (size_t)r * K + cc * 8);
            cp16(bb + (uint32_t)(r * HROW_B + cc * 16),
                 Bsrc + (size_t)r * K + cc * 8);
        }
    };

    const int wid  = tid >> 5;
    const int lane = tid & 31;
    const int wm = wid & 1;
    const int wn = wid >> 1;
    const int g  = lane >> 2;
    const int tg = lane & 3;

    const uint32_t aoff = (uint32_t)((wm * 64 + (lane & 15)) * HROW_B
                                     + ((lane & 16) ? 16 : 0));
    const uint32_t boff = (uint32_t)((wn * 64 + ((lane & 16) ? 8 : 0)
                                      + (lane & 7)) * HROW_B
                                     + ((lane & 8) ? 16 : 0));

    float acc[4][8][4];
#pragma unroll
    for (int mi = 0; mi < 4; mi++)
#pragma unroll
        for (int ni = 0; ni < 8; ni++)
#pragma unroll
            for (int q = 0; q < 4; q++) acc[mi][ni][q] = 0.f;

    load_stage(0, 0);
    asm volatile("cp.async.commit_group;" ::: "memory");
    load_stage(1, 1);
    asm volatile("cp.async.commit_group;" ::: "memory");

    for (int kt = 0; kt < KT; kt++) {
        asm volatile("cp.async.wait_group 1;" ::: "memory");
        __syncthreads();                           // stage kt visible

        uint32_t As = smem_base + (kt & 1) * H_STAGE;
        uint32_t Bs = As + H_TILE_B;

#pragma unroll
        for (int ks = 0; ks < 4; ks++) {
            uint32_t kofs = (uint32_t)ks * 32;
            uint32_t fa[4][4], fb[8][2];
#pragma unroll
            for (int mi = 0; mi < 4; mi++)
                ldsm_x4(fa[mi][0], fa[mi][1], fa[mi][2], fa[mi][3],
                        As + aoff + mi * (16 * HROW_B) + kofs);
#pragma unroll
            for (int nj = 0; nj < 4; nj++)
                ldsm_x4(fb[nj * 2][0], fb[nj * 2][1],
                        fb[nj * 2 + 1][0], fb[nj * 2 + 1][1],
                        Bs + boff + nj * (16 * HROW_B) + kofs);
#pragma unroll
            for (int mi = 0; mi < 4; mi++)
#pragma unroll
                for (int ni = 0; ni < 8; ni++)
                    mma_f16(acc[mi][ni], fa[mi][0], fa[mi][1], fa[mi][2],
                            fa[mi][3], fb[ni][0], fb[ni][1]);
        }

        __syncthreads();                           // all warps done with buf
        if (kt + 2 < KT) load_stage(kt + 2, kt & 1);
        asm volatile("cp.async.commit_group;" ::: "memory");
    }

#pragma unroll
    for (int mi = 0; mi < 4; mi++) {
        int row0 = m0 + wm * 64 + mi * 16 + g;
#pragma unroll
        for (int ni = 0; ni < 8; ni++) {
            int col = n0 + wn * 64 + ni * 8 + tg * 2;
            float2 v0 = make_float2(acc[mi][ni][0], acc[mi][ni][1]);
            float2 v1 = make_float2(acc[mi][ni][2], acc[mi][ni][3]);
            if (BIAS) {
                float2 b2 = *(const float2*)(bias + col);
                v0.x += b2.x; v0.y += b2.y;
                v1.x += b2.x; v1.y += b2.y;
            }
            if (RELU && col < relu_cols) {
                v0.x = fmaxf(v0.x, 0.f); v0.y = fmaxf(v0.y, 0.f);
                v1.x = fmaxf(v1.x, 0.f); v1.y = fmaxf(v1.y, 0.f);
            }
            if constexpr (sizeof(OutT) == 2) {
                *(half2*)((__half*)C + (size_t)row0 * N + col) =
                    __floats2half2_rn(v0.x, v0.y);
                *(half2*)((__half*)C + (size_t)(row0 + 8) * N + col) =
                    __floats2half2_rn(v1.x, v1.y);
            } else {
                *(float2*)((float*)C + (size_t)row0 * N + col) = v0;
                *(float2*)((float*)C + (size_t)(row0 + 8) * N + col) = v1;
            }
        }
    }
}

// ------------------------- K4: kv + ksum via tensor cores --------------------
// kv[d][e] = sum_n phiK[n][d] * V[n][e]; ksum via ones-column MMA in the
// 16B pad region of the VV tile (col64 = 1.0, cols 65-71 = 0; cp.async never
// overwrites the pad, so the init persists across chunk reloads).
constexpr int KVROW_B   = 144;
constexpr int KV_TILE_B = 64 * KVROW_B;            // 9216
constexpr int KV_STAGE  = 2 * KV_TILE_B;           // 18432
constexpr int KV_SMEM   = 3 * KV_STAGE;            // 55296

__global__ __launch_bounds__(128)
void kv_mma_kernel()
{
    extern __shared__ char skv[];
    const uint32_t sb = smem_u32(skv);
    const int tid = threadIdx.x;
    const int wid = tid >> 5;
    const int lane = tid & 31;
    const int split = blockIdx.x;
    const int bh = blockIdx.y;
    const int b = bh >> 4, h = bh & 15;
    const size_t base_row = (size_t)b * 4096 + split * 512;
    const __half* PKg = g_PHIVH + 1024 + h * 64;
    const __half* VVg = g_PHIVH + 2048 + h * 64;

    // init VV pad (col64=1.0h, 65-71=0) for all 3 buffers x 64 rows
    for (int r = tid; r < 192; r += 128) {
        int buf = r >> 6, row = r & 63;
        uint32_t addr = sb + buf * KV_STAGE + KV_TILE_B
                      + (uint32_t)(row * KVROW_B + 128);
        uint4 u = make_uint4(0x00003C00u, 0u, 0u, 0u);
        asm volatile("st.shared.v4.b32 [%0], {%1,%2,%3,%4};"
                     :: "r"(addr), "r"(u.x), "r"(u.y), "r"(u.z), "r"(u.w)
                     : "memory");
    }

    auto load_chunk = [&](int c, int buf) {
        uint32_t pb = sb + buf * KV_STAGE;
        uint32_t vb = pb + KV_TILE_B;
        size_t row0 = base_row + c * 64;
#pragma unroll
        for (int j = 0; j < 4; j++) {
            int o = tid + j * 128;
            int r = o >> 3, cc = o & 7;
            size_t off = (row0 + r) * 3072 + cc * 8;
            cp16(pb + (uint32_t)(r * KVROW_B + cc * 16), PKg + off);
            cp16(vb + (uint32_t)(r * KVROW_B + cc * 16), VVg + off);
        }
    };

    const uint32_t a_off = (uint32_t)((((lane & 16) ? 8 : 0) + (lane & 7)) * KVROW_B
                                      + wid * 32 + ((lane & 8) ? 16 : 0));
    const uint32_t b_off = (uint32_t)((((lane & 8) ? 8 : 0) + (lane & 7)) * KVROW_B
                                      + ((lane & 16) ? 16 : 0));
    // ones-column tile (k16 x n8 at col base 128); lanes 0-15 supply addrs
    const uint32_t s_off = (uint32_t)((((lane & 8) ? 8 : 0) + (lane & 7)) * KVROW_B
                                      + 128);

    float acc[8][4];
#pragma unroll
    for (int ni = 0; ni < 8; ni++)
#pragma unroll
        for (int q = 0; q < 4; q++) acc[ni][q] = 0.f;
    float ks4[4] = {0.f, 0.f, 0.f, 0.f};

    load_chunk(0, 0);
    asm volatile("cp.async.commit_group;" ::: "memory");
    load_chunk(1, 1);
    asm volatile("cp.async.commit_group;" ::: "memory");

    for (int c = 0; c < 8; c++) {
        asm volatile("cp.async.wait_group 1;" ::: "memory");
        __syncthreads();
        if (c + 2 < 8) load_chunk(c + 2, (c + 2) % 3);
        asm volatile("cp.async.commit_group;" ::: "memory");

        uint32_t pb = sb + (c % 3) * KV_STAGE;
        uint32_t vb = pb + KV_TILE_B;

#pragma unroll
        for (int kk = 0; kk < 4; kk++) {
            uint32_t a0, a1, a2, a3;
            ldsm_x4_t(a0, a1, a2, a3, pb + kk * (16 * KVROW_B) + a_off);
#pragma unroll
            for (int eb = 0; eb < 4; eb++) {
                uint32_t r0, r1, r2, r3;
                ldsm_x4_t(r0, r1, r2, r3,
                          vb + kk * (16 * KVROW_B) + b_off + eb * 32);
                mma_f16(acc[eb * 2],     a0, a1, a2, a3, r0, r1);
                mma_f16(acc[eb * 2 + 1], a0, a1, a2, a3, r2, r3);
            }
            // ksum: ones-column tile
            uint32_t s0, s1;
            ldsm_x2_t(s0, s1, vb + kk * (16 * KVROW_B) + s_off);
            mma_f16(ks4, a0, a1, a2, a3, s0, s1);
        }
    }

    float* dst = g_KVP + (size_t)(split * 64 + bh) * 4096;
    int g = lane >> 2, tg = lane & 3;
#pragma unroll
    for (int ni = 0; ni < 8; ni++) {
        int e = ni * 8 + tg * 2;
        int d0 = wid * 16 + g;
        dst[d0 * 64 + e]           = acc[ni][0];
        dst[d0 * 64 + e + 1]       = acc[ni][1];
        dst[(d0 + 8) * 64 + e]     = acc[ni][2];
        dst[(d0 + 8) * 64 + e + 1] = acc[ni][3];
    }
    if (tg == 0) {
        float* ksd = g_KSP + (size_t)(split * 64 + bh) * 64;
        ksd[wid * 16 + g]     = ks4[0];
        ksd[wid * 16 + g + 8] = ks4[2];
    }
}

// ------------------------- K5: vectorized reduction -> fp16 kv [d][e] --------
__global__ __launch_bounds__(256)
void kv_reduce_kernel()
{
    int idx = blockIdx.x * 256 + threadIdx.x;
    if (idx < 65536) {
        int bh = idx >> 10;
        int r4 = (idx & 1023) * 4;
        float4 s = make_float4(0.f, 0.f, 0.f, 0.f);
#pragma unroll
        for (int sp = 0; sp < 8; sp++) {
            float4 v = *(const float4*)(g_KVP
                + (size_t)(sp * 64 + bh) * 4096 + r4);
            s.x += v.x; s.y += v.y; s.z += v.z; s.w += v.w;
        }
        half2 h0 = __floats2half2_rn(s.x, s.y);
        half2 h1 = __floats2half2_rn(s.z, s.w);
        uint2 u = make_uint2(*(uint32_t*)&h0, *(uint32_t*)&h1);
        *(uint2*)(g_KVH + ((size_t)bh << 12) + r4) = u;
    } else {
        int j = idx - 65536;
        if (j < 64 * 64) {
            int bh = j >> 6, d = j & 63;
            float s = 0.f;
#pragma unroll
            for (int sp = 0; sp < 8; sp++)
                s += g_KSP[(sp * 64 + bh) * 64 + d];
            g_KSUM[j] = s;
        }
    }
}

// ------------------------- K6: attn via tensor cores -------------------------
__global__ __launch_bounds__(128)
void attn_mma_kernel()
{
    __shared__ __align__(16) char sPQ[128 * 144];
    __shared__ __align__(16) char sKV[64 * 144];
    __shared__ float sDen[128];
    __shared__ float sKS[64];

    const int tid = threadIdx.x;
    const int wid = tid >> 5;
    const int lane = tid & 31;
    const int chunk = blockIdx.x;
    const int bh = blockIdx.y;
    const int b = bh >> 4, h = bh & 15;
    const size_t m0 = (size_t)b * 4096 + chunk * 128;

    const uint32_t pqb = smem_u32(sPQ);
    const uint32_t kvb = smem_u32(sKV);

    const __half* PQg = g_PHIVH + h * 64;
#pragma unroll
    for (int j = 0; j < 8; j++) {
        int o = tid + j * 128;
        int r = o >> 3, cc = o & 7;
        cp16(pqb + (uint32_t)(r * 144 + cc * 16), PQg + (m0 + r) * 3072 + cc * 8);
    }
    const __half* KVg = g_KVH + ((size_t)bh << 12);
#pragma unroll
    for (int j = 0; j < 4; j++) {
        int o = tid + j * 128;
        int r = o >> 3, cc = o & 7;
        cp16(kvb + (uint32_t)(r * 144 + cc * 16), KVg + r * 64 + cc * 8);
    }
    asm volatile("cp.async.commit_group;" ::: "memory");
    if (tid < 64) sKS[tid] = g_KSUM[bh * 64 + tid];
    asm volatile("cp.async.wait_group 0;" ::: "memory");
    __syncthreads();

    {
        const __half* pq = (const __half*)(sPQ + tid * 144);
        float den = 0.f;
#pragma unroll 16
        for (int d = 0; d < 64; d++)
            den += __half2float(pq[d]) * sKS[d];
        sDen[tid] = 1.0f / (0.125f * den + 1e-8f);
    }

    const uint32_t aoff = pqb + (uint32_t)((wid * 32 + (lane & 15)) * 144
                                           + ((lane & 16) ? 16 : 0));
    const uint32_t boff = kvb + (uint32_t)((((lane & 8) ? 8 : 0) + (lane & 7)) * 144
                                           + ((lane & 16) ? 16 : 0));

    float acc[2][8][4];
#pragma unroll
    for (int mi = 0; mi < 2; mi++)
#pragma unroll
        for (int ni = 0; ni < 8; ni++)
#pragma unroll
            for (int q = 0; q < 4; q++) acc[mi][ni][q] = 0.f;

#pragma unroll
    for (int ksb = 0; ksb < 4; ksb++) {
        uint32_t af[2][4];
#pragma unroll
        for (int mi = 0; mi < 2; mi++)
            ldsm_x4(af[mi][0], af[mi][1], af[mi][2], af[mi][3],
                    aoff + mi * (16 * 144) + ksb * 32);
        uint32_t bf[8][2];
#pragma unroll
        for (int nj = 0; nj < 4; nj++)
            ldsm_x4_t(bf[nj * 2][0], bf[nj * 2][1],
                      bf[nj * 2 + 1][0], bf[nj * 2 + 1][1],
                      boff + ksb * (16 * 144) + nj * 32);
#pragma unroll
        for (int mi = 0; mi < 2; mi++)
#pragma unroll
            for (int ni = 0; ni < 8; ni++)
                mma_f16(acc[mi][ni], af[mi][0], af[mi][1], af[mi][2],
                        af[mi][3], bf[ni][0], bf[ni][1]);
    }
    __syncthreads();

    const int g = lane >> 2, tg = lane & 3;
#pragma unroll
    for (int mi = 0; mi < 2; mi++) {
        int row = wid * 32 + mi * 16 + g;
        float inv0 = sDen[row], inv1 = sDen[row + 8];
        __half* dst0 = g_ATTNH + (m0 + row) * 1024 + h * 64;
#pragma unroll
        for (int ni = 0; ni < 8; ni++) {
            int e = ni * 8 + tg * 2;
            *(half2*)(dst0 + e) =
                __floats2half2_rn(acc[mi][ni][0] * inv0, acc[mi][ni][1] * inv0);
            *(half2*)(dst0 + 8 * 1024 + e) =
                __floats2half2_rn(acc[mi][ni][2] * inv1, acc[mi][ni][3] * inv1);
        }
    }
}

// ------------------------- launch -------------------------------------------
extern "C" void kernel_launch(void* const* d_in, const int* in_sizes, int n_in,
                              void* d_out, int out_size)
{
    const float* query = (const float*)d_in[0];
    const float* Wq    = (const float*)d_in[1];
    const float* Wk    = (const float*)d_in[2];
    const float* Wv    = (const float*)d_in[3];
    const float* P     = (const float*)d_in[4];
    const float* Wo    = (const float*)d_in[5];
    const float* bo    = (const float*)d_in[6];
    float* out = (float*)d_out;

    void *p_xh, *p_wbigh, *p_worh, *p_attnh, *p_phivh;
    cudaGetSymbolAddress(&p_xh,     g_XH);
    cudaGetSymbolAddress(&p_wbigh,  g_WBIGH);
    cudaGetSymbolAddress(&p_worh,   g_WORH);
    cudaGetSymbolAddress(&p_attnh,  g_ATTNH);
    cudaGetSymbolAddress(&p_phivh,  g_PHIVH);

    cudaFuncSetAttribute((const void*)gemm_mma<__half, true, false>,
                         cudaFuncAttributeMaxDynamicSharedMemorySize, GEMM_SMEM);
    cudaFuncSetAttribute((const void*)gemm_mma<float, false, true>,
                         cudaFuncAttributeMaxDynamicSharedMemorySize, GEMM_SMEM);
    cudaFuncSetAttribute((const void*)kv_mma_kernel,
                         cudaFuncAttributeMaxDynamicSharedMemorySize, KV_SMEM);

    // fused prologue: weff + Wv copy + Wo round + query round, one launch
    prologue_kernel<<<10240, 256>>>(Wq, Wk, P, Wv, query, Wo);

    // PHIVH = relu(XH @ WBIGH^T) on first 2048 cols (fp16 out)
    gemm_mma<__half, true, false><<<dim3(24, 128), 128, GEMM_SMEM>>>(
        (const __half*)p_xh, (const __half*)p_wbigh, nullptr,
        (__half*)p_phivh, 16384, 3072, 1024, 2048);

    kv_mma_kernel<<<dim3(8, 64), 128, KV_SMEM>>>();
    kv_reduce_kernel<<<272, 256>>>();
    attn_mma_kernel<<<dim3(32, 64), 128>>>();   // writes fp16 ATTN

    // out = ATTNH @ WORH^T + bo (fp32 out)
    gemm_mma<float, false, true><<<dim3(8, 128), 128, GEMM_SMEM>>>(
        (const __half*)p_attnh, (const __half*)p_worh, bo, out,
        16384, 1024, 1024, 0);
}